// round 6
// baseline (speedup 1.0000x reference)
#include <cuda_runtime.h>
#include <cuda_bf16.h>
#include <cstdint>
#include <cstddef>

// Problem constants
#define B_  64
#define T_  320
#define E_  1024
#define H_  16
#define HS_ 64
#define M_  (B_*T_)      // 20480 tokens
#define FF_ (4*E_)       // 4096

// ---------------- device scratch (allocation-free rule: __device__ globals) ---
__device__ float g_h   [(size_t)M_*E_];   // LN output (reused for LN1 and LN2)
__device__ float g_q   [(size_t)M_*E_];   // [B,H,T,HS]
__device__ float g_k   [(size_t)M_*E_];
__device__ float g_v   [(size_t)M_*E_];
__device__ float g_attn[(size_t)M_*E_];   // [B,T,H,HS] == [M,E]
__device__ float g_ffn1[(size_t)M_*FF_];  // relu(h2@W1+b1)
__device__ float g_wqkv[(size_t)E_*3*E_]; // packed QKV weights [E, 3E]

// ---------------- pack Wq/Wk/Wv (H,E,HS) -> Wp[E][3E] --------------------------
__global__ void pack_qkv_kernel(const float* __restrict__ Wq,
                                const float* __restrict__ Wk,
                                const float* __restrict__ Wv,
                                float* __restrict__ Wp)
{
    int idx = blockIdx.x * blockDim.x + threadIdx.x;   // over E*3E = 3,145,728
    if (idx >= E_ * 3 * E_) return;
    int e = idx / (3 * E_);
    int n = idx - e * (3 * E_);
    int which = n >> 10;           // 0=q 1=k 2=v
    int w = n & (E_ - 1);
    int h = w >> 6;
    int d = w & (HS_ - 1);
    const float* W = (which == 0) ? Wq : (which == 1) ? Wk : Wv;
    Wp[idx] = W[((size_t)h * E_ + e) * HS_ + d];
}

// ---------------- layernorm: one block per row of 1024 -------------------------
__global__ void __launch_bounds__(256) ln_kernel(const float* __restrict__ x,
                                                 const float* __restrict__ w,
                                                 const float* __restrict__ b,
                                                 float* __restrict__ o)
{
    int row = blockIdx.x;
    int t = threadIdx.x;
    const float4* xr = (const float4*)(x + (size_t)row * E_);
    float4 v = xr[t];
    float s  = v.x + v.y + v.z + v.w;
    float sq = v.x*v.x + v.y*v.y + v.z*v.z + v.w*v.w;
    #pragma unroll
    for (int off = 16; off; off >>= 1) {
        s  += __shfl_xor_sync(0xffffffffu, s,  off);
        sq += __shfl_xor_sync(0xffffffffu, sq, off);
    }
    __shared__ float ss[8], ssq[8];
    int warp = t >> 5, lane = t & 31;
    if (lane == 0) { ss[warp] = s; ssq[warp] = sq; }
    __syncthreads();
    float tot = 0.f, totq = 0.f;
    #pragma unroll
    for (int i = 0; i < 8; i++) { tot += ss[i]; totq += ssq[i]; }
    float mu  = tot * (1.0f / E_);
    float var = totq * (1.0f / E_) - mu * mu;
    float rs  = rsqrtf(var + 1e-5f);
    float4 w4 = ((const float4*)w)[t];
    float4 b4 = ((const float4*)b)[t];
    float4 r;
    r.x = (v.x - mu) * rs * w4.x + b4.x;
    r.y = (v.y - mu) * rs * w4.y + b4.y;
    r.z = (v.z - mu) * rs * w4.z + b4.z;
    r.w = (v.w - mu) * rs * w4.w + b4.w;
    ((float4*)(o + (size_t)row * E_))[t] = r;
}

// ---------------- tiled SGEMM 128x128x8, 256 thr, 8x8/thread -------------------
// EPI 0: scatter into q/k/v  (N=3E packed)
// EPI 1: C = acc + bias[n] + resid[m*N+n]
// EPI 2: C = relu(acc + bias[n])
template<int EPI>
__global__ void __launch_bounds__(256) sgemm_kernel(
    const float* __restrict__ A, const float* __restrict__ B,
    float* __restrict__ C, int M, int N, int K,
    const float* __restrict__ bias, const float* __restrict__ resid,
    float* __restrict__ qo, float* __restrict__ ko, float* __restrict__ vo)
{
    __shared__ float As[8][128];
    __shared__ float Bs[8][128];
    int bm = blockIdx.y, bn = blockIdx.x;
    int tid = threadIdx.x;

    int arow  = tid >> 1;          // 128 rows, 2 thr/row
    int acol4 = (tid & 1) * 4;
    int brow  = tid >> 5;          // 8 rows
    int bcol4 = (tid & 31) * 4;

    const float* Aptr = A + ((size_t)bm * 128 + arow) * K + acol4;
    const float* Bptr = B + (size_t)brow * N + (size_t)bn * 128 + bcol4;

    float acc[8][8];
    #pragma unroll
    for (int i = 0; i < 8; i++)
        #pragma unroll
        for (int j = 0; j < 8; j++) acc[i][j] = 0.f;

    int tm = tid >> 4, tn = tid & 15;

    for (int k0 = 0; k0 < K; k0 += 8) {
        float4 a  = *(const float4*)Aptr;
        float4 bb = *(const float4*)Bptr;
        As[acol4 + 0][arow] = a.x;
        As[acol4 + 1][arow] = a.y;
        As[acol4 + 2][arow] = a.z;
        As[acol4 + 3][arow] = a.w;
        *(float4*)&Bs[brow][bcol4] = bb;
        __syncthreads();

        #pragma unroll
        for (int kk = 0; kk < 8; kk++) {
            float4 a0 = *(const float4*)&As[kk][tm * 8];
            float4 a1 = *(const float4*)&As[kk][tm * 8 + 4];
            float4 b0 = *(const float4*)&Bs[kk][tn * 8];
            float4 b1 = *(const float4*)&Bs[kk][tn * 8 + 4];
            float ar[8] = {a0.x, a0.y, a0.z, a0.w, a1.x, a1.y, a1.z, a1.w};
            float br[8] = {b0.x, b0.y, b0.z, b0.w, b1.x, b1.y, b1.z, b1.w};
            #pragma unroll
            for (int i = 0; i < 8; i++)
                #pragma unroll
                for (int j = 0; j < 8; j++)
                    acc[i][j] += ar[i] * br[j];
        }
        __syncthreads();
        Aptr += 8;
        Bptr += (size_t)8 * N;
    }

    int gm0 = bm * 128 + tm * 8;
    int gn0 = bn * 128 + tn * 8;

    #pragma unroll
    for (int i = 0; i < 8; i++) {
        int gm = gm0 + i;
        #pragma unroll
        for (int j = 0; j < 8; j++) {
            int gn = gn0 + j;
            float val = acc[i][j];
            if (EPI == 0) {
                int which = gn >> 10;
                int w = gn & (E_ - 1);
                int hh = w >> 6;
                int dd = w & (HS_ - 1);
                int bbk = gm / T_;
                int tt = gm - bbk * T_;
                float* dst = (which == 0) ? qo : (which == 1) ? ko : vo;
                dst[(((size_t)(bbk * H_ + hh)) * T_ + tt) * HS_ + dd] = val;
            } else if (EPI == 1) {
                C[(size_t)gm * N + gn] = val + bias[gn] + resid[(size_t)gm * N + gn];
            } else {
                float r = val + bias[gn];
                C[(size_t)gm * N + gn] = fmaxf(r, 0.f);
            }
        }
    }
}

// ---------------- flash attention: 32q x 32k tiles, HS=64 ----------------------
// grid: (qtiles=10, B*H=1024), block 256
__global__ void __launch_bounds__(256) attn_kernel(
    const float* __restrict__ Qg, const float* __restrict__ Kg,
    const float* __restrict__ Vg, float* __restrict__ Og)
{
    __shared__ float Qs[32][65];
    __shared__ float Kst[64][33];   // transposed: [d][kc]
    __shared__ float Vs[32][64];
    __shared__ float Ps[32][33];

    int bh = blockIdx.y;
    int q0 = blockIdx.x * 32;
    const float* qbase = Qg + (size_t)bh * T_ * HS_;
    const float* kbase = Kg + (size_t)bh * T_ * HS_;
    const float* vbase = Vg + (size_t)bh * T_ * HS_;

    int tid = threadIdx.x;
    int r   = tid >> 3;            // 0..31: row for loads / S / O
    int c8  = (tid & 7) * 8;       // 0..56 step 8
    int kc0 = (tid & 7) * 4;       // S columns
    int grow = q0 + r;

    // load Q tile
    {
        const float* src = qbase + (size_t)grow * HS_ + c8;
        #pragma unroll
        for (int i = 0; i < 8; i++) Qs[r][c8 + i] = src[i];
    }

    float acc[8];
    #pragma unroll
    for (int i = 0; i < 8; i++) acc[i] = 0.f;
    float m_i = -1e30f, l_i = 0.f;

    int ntiles = blockIdx.x + 1;
    for (int kt = 0; kt < ntiles; kt++) {
        __syncthreads();   // prior-iter reads done before overwriting K/V
        {
            const float* ks = kbase + (size_t)(kt * 32 + r) * HS_ + c8;
            const float* vs = vbase + (size_t)(kt * 32 + r) * HS_ + c8;
            #pragma unroll
            for (int i = 0; i < 8; i++) Kst[c8 + i][r] = ks[i];
            #pragma unroll
            for (int i = 0; i < 8; i++) Vs[r][c8 + i] = vs[i];
        }
        __syncthreads();

        // S = Q K^T * scale, 4 columns per thread
        float s[4] = {0.f, 0.f, 0.f, 0.f};
        #pragma unroll 8
        for (int d = 0; d < 64; d++) {
            float a = Qs[r][d];
            #pragma unroll
            for (int j = 0; j < 4; j++) s[j] += a * Kst[d][kc0 + j];
        }
        #pragma unroll
        for (int j = 0; j < 4; j++) {
            s[j] *= 0.03125f;   // E^-0.5 = 1/32
            int gc = kt * 32 + kc0 + j;
            if (gc > grow) s[j] = -1e30f;
        }

        // running softmax stats: reduce over the 8-lane group sharing a row
        float tm = fmaxf(fmaxf(s[0], s[1]), fmaxf(s[2], s[3]));
        #pragma unroll
        for (int off = 4; off; off >>= 1)
            tm = fmaxf(tm, __shfl_xor_sync(0xffffffffu, tm, off, 8));
        float m_new = fmaxf(m_i, tm);
        float alpha = __expf(m_i - m_new);
        float ps = 0.f;
        #pragma unroll
        for (int j = 0; j < 4; j++) {
            float p = __expf(s[j] - m_new);
            Ps[r][kc0 + j] = p;
            ps += p;
        }
        #pragma unroll
        for (int off = 4; off; off >>= 1)
            ps += __shfl_xor_sync(0xffffffffu, ps, off, 8);
        l_i = l_i * alpha + ps;
        m_i = m_new;
        __syncthreads();   // Ps visible

        #pragma unroll
        for (int i = 0; i < 8; i++) acc[i] *= alpha;
        #pragma unroll 4
        for (int j = 0; j < 32; j++) {
            float p = Ps[r][j];
            const float4* vrow = (const float4*)&Vs[j][c8];
            float4 v0 = vrow[0];
            float4 v1 = vrow[1];
            acc[0] += p * v0.x; acc[1] += p * v0.y;
            acc[2] += p * v0.z; acc[3] += p * v0.w;
            acc[4] += p * v1.x; acc[5] += p * v1.y;
            acc[6] += p * v1.z; acc[7] += p * v1.w;
        }
    }

    float inv = 1.0f / l_i;
    int b = bh >> 4, h = bh & 15;
    float* dst = Og + (((size_t)(b * T_ + grow)) * H_ + h) * HS_ + c8;
    #pragma unroll
    for (int i = 0; i < 8; i++) dst[i] = acc[i] * inv;
}

// ---------------- launch --------------------------------------------------------
extern "C" void kernel_launch(void* const* d_in, const int* in_sizes, int n_in,
                              void* d_out, int out_size)
{
    const float* x    = (const float*)d_in[0];
    const float* Wq   = (const float*)d_in[1];
    const float* Wk   = (const float*)d_in[2];
    const float* Wv   = (const float*)d_in[3];
    const float* Wo   = (const float*)d_in[4];
    const float* bo   = (const float*)d_in[5];
    const float* W1   = (const float*)d_in[6];
    const float* b1   = (const float*)d_in[7];
    const float* W2   = (const float*)d_in[8];
    const float* b2   = (const float*)d_in[9];
    const float* ln1w = (const float*)d_in[10];
    const float* ln1b = (const float*)d_in[11];
    const float* ln2w = (const float*)d_in[12];
    const float* ln2b = (const float*)d_in[13];
    float* out = (float*)d_out;

    float *p_h, *p_q, *p_k, *p_v, *p_attn, *p_ffn1, *p_wqkv;
    cudaGetSymbolAddress((void**)&p_h,    g_h);
    cudaGetSymbolAddress((void**)&p_q,    g_q);
    cudaGetSymbolAddress((void**)&p_k,    g_k);
    cudaGetSymbolAddress((void**)&p_v,    g_v);
    cudaGetSymbolAddress((void**)&p_attn, g_attn);
    cudaGetSymbolAddress((void**)&p_ffn1, g_ffn1);
    cudaGetSymbolAddress((void**)&p_wqkv, g_wqkv);

    // 1. pack QKV weights: (H,E,HS)x3 -> [E, 3E]
    pack_qkv_kernel<<<(E_ * 3 * E_ + 255) / 256, 256>>>(Wq, Wk, Wv, p_wqkv);

    // 2. h = LN1(x)
    ln_kernel<<<M_, 256>>>(x, ln1w, ln1b, p_h);

    // 3. q,k,v = h @ Wqkv  (scatter into [B,H,T,HS])
    sgemm_kernel<0><<<dim3(3 * E_ / 128, M_ / 128), 256>>>(
        p_h, p_wqkv, nullptr, M_, 3 * E_, E_, nullptr, nullptr, p_q, p_k, p_v);

    // 4. attention -> [B,T,H,HS]
    attn_kernel<<<dim3(T_ / 32, B_ * H_), 256>>>(p_q, p_k, p_v, p_attn);

    // 5. x1 = x + attn @ Wo + bo     (into d_out)
    sgemm_kernel<1><<<dim3(E_ / 128, M_ / 128), 256>>>(
        p_attn, Wo, out, M_, E_, E_, bo, x, nullptr, nullptr, nullptr);

    // 6. h2 = LN2(x1)
    ln_kernel<<<M_, 256>>>(out, ln2w, ln2b, p_h);

    // 7. ffn1 = relu(h2 @ W1 + b1)
    sgemm_kernel<2><<<dim3(FF_ / 128, M_ / 128), 256>>>(
        p_h, W1, p_ffn1, M_, FF_, E_, b1, nullptr, nullptr, nullptr, nullptr);

    // 8. out = x1 + ffn1 @ W2 + b2   (reads x1 from d_out, writes d_out)
    sgemm_kernel<1><<<dim3(E_ / 128, M_ / 128), 256>>>(
        p_ffn1, W2, out, M_, E_, FF_, b2, out, nullptr, nullptr, nullptr);
}

// round 10
// speedup vs baseline: 2.5581x; 2.5581x over previous
#include <cuda_runtime.h>
#include <cuda_bf16.h>
#include <cstdint>
#include <cstddef>

// Problem constants
#define B_  64
#define T_  320
#define E_  1024
#define H_  16
#define HS_ 64
#define M_  (B_*T_)      // 20480 tokens
#define FF_ (4*E_)       // 4096

// ===================== baseline-PTX helpers (no 'a'-arch features!) ============
__device__ __forceinline__ uint32_t smem_to_u32(const void* p) {
    uint32_t a;
    asm("{ .reg .u64 t; cvta.to.shared.u64 t, %1; cvt.u32.u64 %0, t; }" : "=r"(a) : "l"(p));
    return a;
}
__device__ __forceinline__ void cp16(uint32_t s, const void* g) {
    asm volatile("cp.async.cg.shared.global [%0], [%1], 16;" :: "r"(s), "l"(g));
}
#define CP_COMMIT() asm volatile("cp.async.commit_group;" ::: "memory")
#define CP_WAIT1()  asm volatile("cp.async.wait_group 1;"  ::: "memory")

__device__ __forceinline__ void ldsm4(uint32_t* r, uint32_t addr) {
    asm volatile("ldmatrix.sync.aligned.m8n8.x4.shared.b16 {%0,%1,%2,%3}, [%4];"
        : "=r"(r[0]), "=r"(r[1]), "=r"(r[2]), "=r"(r[3]) : "r"(addr));
}
__device__ __forceinline__ void mma16816(float* c, const uint32_t* a,
                                         uint32_t b0, uint32_t b1) {
    asm volatile(
        "mma.sync.aligned.m16n8k16.row.col.f32.bf16.bf16.f32 "
        "{%0,%1,%2,%3},{%4,%5,%6,%7},{%8,%9},{%0,%1,%2,%3};"
        : "+f"(c[0]), "+f"(c[1]), "+f"(c[2]), "+f"(c[3])
        : "r"(a[0]), "r"(a[1]), "r"(a[2]), "r"(a[3]), "r"(b0), "r"(b1));
}

// ===================== device scratch (no allocations allowed) ==================
__device__ __nv_bfloat16 g_h_hi   [(size_t)M_*E_];
__device__ __nv_bfloat16 g_h_lo   [(size_t)M_*E_];
__device__ __nv_bfloat16 g_at_hi  [(size_t)M_*E_];
__device__ __nv_bfloat16 g_at_lo  [(size_t)M_*E_];
__device__ __nv_bfloat16 g_f1_hi  [(size_t)M_*FF_];
__device__ __nv_bfloat16 g_f1_lo  [(size_t)M_*FF_];
__device__ float         g_q      [(size_t)M_*E_];
__device__ float         g_k      [(size_t)M_*E_];
__device__ float         g_v      [(size_t)M_*E_];
__device__ __nv_bfloat16 g_wqkv_hi[(size_t)3*E_*E_];   // [N=3E, K=E]
__device__ __nv_bfloat16 g_wqkv_lo[(size_t)3*E_*E_];
__device__ __nv_bfloat16 g_wo_hi  [(size_t)E_*E_];     // [N=E, K=E]
__device__ __nv_bfloat16 g_wo_lo  [(size_t)E_*E_];
__device__ __nv_bfloat16 g_w1_hi  [(size_t)FF_*E_];    // [N=4E, K=E]
__device__ __nv_bfloat16 g_w1_lo  [(size_t)FF_*E_];
__device__ __nv_bfloat16 g_w2_hi  [(size_t)E_*FF_];    // [N=E, K=4E]
__device__ __nv_bfloat16 g_w2_lo  [(size_t)E_*FF_];

__device__ __forceinline__ void split_bf16(float v, __nv_bfloat16& hi, __nv_bfloat16& lo) {
    hi = __float2bfloat16(v);
    lo = __float2bfloat16(v - __bfloat162float(hi));
}

// ============ weight prep: transpose fp32 [K,N] -> bf16 hi/lo [N,K] =============
__global__ void trans_split_kernel(const float* __restrict__ in, int K, int N,
                                   __nv_bfloat16* __restrict__ ohi,
                                   __nv_bfloat16* __restrict__ olo)
{
    __shared__ float t[32][33];
    int nb = blockIdx.x * 32, kb = blockIdx.y * 32;
    int tx = threadIdx.x, ty = threadIdx.y;          // 32 x 8
    #pragma unroll
    for (int j = 0; j < 4; j++)
        t[ty + j*8][tx] = in[(size_t)(kb + ty + j*8) * N + nb + tx];
    __syncthreads();
    #pragma unroll
    for (int j = 0; j < 4; j++) {
        float v = t[tx][ty + j*8];
        int orow = nb + ty + j*8, ocol = kb + tx;
        __nv_bfloat16 hi, lo; split_bf16(v, hi, lo);
        ohi[(size_t)orow * K + ocol] = hi;
        olo[(size_t)orow * K + ocol] = lo;
    }
}

// Wq/Wk/Wv (H,E,HS) -> [3E rows, E cols] transposed split
__global__ void trans_qkv_kernel(const float* __restrict__ Wq,
                                 const float* __restrict__ Wk,
                                 const float* __restrict__ Wv,
                                 __nv_bfloat16* __restrict__ ohi,
                                 __nv_bfloat16* __restrict__ olo)
{
    __shared__ float t[32][33];
    int z = blockIdx.z;                               // which*16 + h
    const float* W = (z < 16) ? Wq : (z < 32) ? Wk : Wv;
    const float* in = W + (size_t)(z & 15) * E_ * HS_;  // [E, 64]
    int nb = blockIdx.x * 32, kb = blockIdx.y * 32;
    int tx = threadIdx.x, ty = threadIdx.y;
    #pragma unroll
    for (int j = 0; j < 4; j++)
        t[ty + j*8][tx] = in[(size_t)(kb + ty + j*8) * HS_ + nb + tx];
    __syncthreads();
    #pragma unroll
    for (int j = 0; j < 4; j++) {
        float v = t[tx][ty + j*8];
        int orow = z * 64 + nb + ty + j*8;            // output N row
        int ocol = kb + tx;                           // K
        __nv_bfloat16 hi, lo; split_bf16(v, hi, lo);
        ohi[(size_t)orow * E_ + ocol] = hi;
        olo[(size_t)orow * E_ + ocol] = lo;
    }
}

// ================= layernorm -> split bf16 hi/lo =================================
__global__ void __launch_bounds__(256) ln_kernel(const float* __restrict__ x,
                                                 const float* __restrict__ w,
                                                 const float* __restrict__ b,
                                                 __nv_bfloat16* __restrict__ ohi,
                                                 __nv_bfloat16* __restrict__ olo)
{
    int row = blockIdx.x;
    int t = threadIdx.x;
    float4 v = ((const float4*)(x + (size_t)row * E_))[t];
    float s  = v.x + v.y + v.z + v.w;
    float sq = v.x*v.x + v.y*v.y + v.z*v.z + v.w*v.w;
    #pragma unroll
    for (int off = 16; off; off >>= 1) {
        s  += __shfl_xor_sync(0xffffffffu, s,  off);
        sq += __shfl_xor_sync(0xffffffffu, sq, off);
    }
    __shared__ float ss[8], ssq[8];
    int warp = t >> 5, lane = t & 31;
    if (lane == 0) { ss[warp] = s; ssq[warp] = sq; }
    __syncthreads();
    float tot = 0.f, totq = 0.f;
    #pragma unroll
    for (int i = 0; i < 8; i++) { tot += ss[i]; totq += ssq[i]; }
    float mu  = tot * (1.0f / E_);
    float var = totq * (1.0f / E_) - mu * mu;
    float rs  = rsqrtf(var + 1e-5f);
    float4 w4 = ((const float4*)w)[t];
    float4 b4 = ((const float4*)b)[t];
    float r0 = (v.x - mu) * rs * w4.x + b4.x;
    float r1 = (v.y - mu) * rs * w4.y + b4.y;
    float r2 = (v.z - mu) * rs * w4.z + b4.z;
    float r3 = (v.w - mu) * rs * w4.w + b4.w;
    __nv_bfloat16 h0,l0,h1,l1,h2,l2,h3,l3;
    split_bf16(r0,h0,l0); split_bf16(r1,h1,l1); split_bf16(r2,h2,l2); split_bf16(r3,h3,l3);
    __nv_bfloat162 hh0 = {h0, h1}, hh1 = {h2, h3};
    __nv_bfloat162 ll0 = {l0, l1}, ll1 = {l2, l3};
    uint2 hp = { *(uint32_t*)&hh0, *(uint32_t*)&hh1 };
    uint2 lp = { *(uint32_t*)&ll0, *(uint32_t*)&ll1 };
    ((uint2*)(ohi + (size_t)row * E_))[t] = hp;
    ((uint2*)(olo + (size_t)row * E_))[t] = lp;
}

// ================= mma.sync split-bf16 GEMM =====================================
// C[M,N] = A[M,K] * B[N,K]^T. 128x128 tile, K-chunk 32, 8 warps (2x4),
// warp tile 64x32 = 4x4 m16n8k16 atoms, 3-stage cp.async pipeline.
// Split-bf16: acc += Ahi*Bhi + Ahi*Blo + Alo*Bhi  (fp32 register accum).
// EPI 0: scatter fp32 to q/k/v   EPI 1: fp32 out = acc+bias+resid
// EPI 2: bf16 hi/lo out = split(relu(acc+bias))

#define ST_HALF  8192                  // 128 rows x 64B
#define STAGE_B  (4*ST_HALF)           // Ahi,Alo,Bhi,Blo
#define NSTAGE   3
#define SMEM_GEMM (NSTAGE*STAGE_B)     // 96 KB

// XOR swizzle: row pitch 64B, chunk index cb (0..3, 16B units)
__device__ __forceinline__ uint32_t swz(int row, int cb) {
    return (uint32_t)((row << 6) + ((cb ^ ((row >> 1) & 3)) << 4));
}

template<int EPI>
__global__ void __launch_bounds__(256) tgemm_kernel(
    const __nv_bfloat16* __restrict__ Ahi, const __nv_bfloat16* __restrict__ Alo,
    const __nv_bfloat16* __restrict__ Bhi, const __nv_bfloat16* __restrict__ Blo,
    int M, int N, int K,
    const float* __restrict__ bias, const float* __restrict__ resid,
    float* __restrict__ outf,
    __nv_bfloat16* __restrict__ ohi, __nv_bfloat16* __restrict__ olo,
    float* __restrict__ qo, float* __restrict__ ko, float* __restrict__ vo)
{
    extern __shared__ char smem[];
    uint32_t sb = smem_to_u32(smem);
    int tid  = threadIdx.x;
    int lane = tid & 31, wid = tid >> 5;
    int bm = blockIdx.y, bn = blockIdx.x;
    int wm = wid >> 2, wn = wid & 3;

    const char* pAhi = (const char*)Ahi;
    const char* pAlo = (const char*)Alo;
    const char* pBhi = (const char*)Bhi;
    const char* pBlo = (const char*)Blo;
    const int K2 = K * 2;                       // bytes per K-row
    const size_t aBase = (size_t)(bm * 128) * K2;
    const size_t bBase = (size_t)(bn * 128) * K2;
    const int nch = K >> 5;                     // K-chunks of 32

    // per-thread load coords: 2 x 16B chunks per operand-half per stage
    int rr0 = tid >> 2,        cb0 = tid & 3;          // idx = tid
    int rr1 = (tid + 256) >> 2, cb1 = tid & 3;         // idx = tid+256

    // ldmatrix coords
    int a_row  = wm * 64 + (lane & 15);
    int a_cbo  = lane >> 4;                     // 0/1
    int bg = lane >> 3, br = lane & 7;
    int b_row  = wn * 32 + ((bg >> 1) << 3) + br;
    int b_cbo  = bg & 1;

    float acc[4][4][4];
    #pragma unroll
    for (int a = 0; a < 4; a++)
        #pragma unroll
        for (int nb = 0; nb < 4; nb++)
            #pragma unroll
            for (int i = 0; i < 4; i++) acc[a][nb][i] = 0.f;

    // ---- loader lambda-ish macro ----
    #define LOAD_STAGE(sidx, kb) do {                                              \
        uint32_t s_ = sb + (uint32_t)(sidx) * STAGE_B;                              \
        uint32_t o0 = swz(rr0, cb0), o1 = swz(rr1, cb1);                            \
        size_t ga0 = aBase + (size_t)rr0 * K2 + (kb) + cb0 * 16;                    \
        size_t ga1 = aBase + (size_t)rr1 * K2 + (kb) + cb1 * 16;                    \
        size_t gb0 = bBase + (size_t)rr0 * K2 + (kb) + cb0 * 16;                    \
        size_t gb1 = bBase + (size_t)rr1 * K2 + (kb) + cb1 * 16;                    \
        cp16(s_ + o0,             pAhi + ga0);                                      \
        cp16(s_ + o1,             pAhi + ga1);                                      \
        cp16(s_ + ST_HALF + o0,   pAlo + ga0);                                      \
        cp16(s_ + ST_HALF + o1,   pAlo + ga1);                                      \
        cp16(s_ + 2*ST_HALF + o0, pBhi + gb0);                                      \
        cp16(s_ + 2*ST_HALF + o1, pBhi + gb1);                                      \
        cp16(s_ + 3*ST_HALF + o0, pBlo + gb0);                                      \
        cp16(s_ + 3*ST_HALF + o1, pBlo + gb1);                                      \
    } while (0)

    // prologue: 2 stages in flight
    LOAD_STAGE(0, 0);   CP_COMMIT();
    LOAD_STAGE(1, 64);  CP_COMMIT();

    int sidx = 0;
    for (int c = 0; c < nch; c++) {
        CP_WAIT1();
        __syncthreads();
        // prefetch chunk c+2
        if (c + 2 < nch) {
            int nsi = sidx + 2; if (nsi >= NSTAGE) nsi -= NSTAGE;
            LOAD_STAGE(nsi, (size_t)(c + 2) * 64);
        }
        CP_COMMIT();

        uint32_t s = sb + (uint32_t)sidx * STAGE_B;
        #pragma unroll
        for (int ks = 0; ks < 2; ks++) {
            uint32_t ahi[4][4], alo[4][4];
            int acb = ks * 2 + a_cbo;
            #pragma unroll
            for (int a = 0; a < 4; a++) {
                uint32_t ad = s + swz(a_row + a * 16, acb);
                ldsm4(ahi[a], ad);
                ldsm4(alo[a], ad + ST_HALF);
            }
            uint32_t bhi[2][4], blo[2][4];
            int bcb = ks * 2 + b_cbo;
            #pragma unroll
            for (int p = 0; p < 2; p++) {
                uint32_t bd = s + 2 * ST_HALF + swz(b_row + p * 16, bcb);
                ldsm4(bhi[p], bd);
                ldsm4(blo[p], bd + ST_HALF);
            }
            #pragma unroll
            for (int a = 0; a < 4; a++)
                #pragma unroll
                for (int p = 0; p < 2; p++)
                    #pragma unroll
                    for (int h = 0; h < 2; h++) {
                        int nb = p * 2 + h;
                        mma16816(acc[a][nb], ahi[a], bhi[p][2*h], bhi[p][2*h+1]);
                        mma16816(acc[a][nb], ahi[a], blo[p][2*h], blo[p][2*h+1]);
                        mma16816(acc[a][nb], alo[a], bhi[p][2*h], bhi[p][2*h+1]);
                    }
        }
        sidx++; if (sidx >= NSTAGE) sidx = 0;
    }
    #undef LOAD_STAGE

    // ---- epilogue: C fragment (m=lane/4 [+8], n=2*(lane%4)+{0,1}) --------------
    int erow0 = bm * 128 + wm * 64 + (lane >> 2);
    int ecol0 = bn * 128 + wn * 32 + 2 * (lane & 3);

    #pragma unroll
    for (int a = 0; a < 4; a++) {
        #pragma unroll
        for (int nb = 0; nb < 4; nb++) {
            int gn = ecol0 + nb * 8;
            #pragma unroll
            for (int half = 0; half < 2; half++) {
                int gm = erow0 + a * 16 + half * 8;
                float v0 = acc[a][nb][half * 2 + 0];
                float v1 = acc[a][nb][half * 2 + 1];
                if (EPI == 0) {
                    int which = gn >> 10;
                    int w = gn & (E_ - 1);
                    int hh = w >> 6, dd = w & 63;
                    int bk = gm / T_, tt = gm - bk * T_;
                    float* dst = (which == 0) ? qo : (which == 1) ? ko : vo;
                    float2 o = {v0, v1};
                    *(float2*)(dst + (((size_t)(bk * H_ + hh)) * T_ + tt) * HS_ + dd) = o;
                } else if (EPI == 1) {
                    const float2 bv = *(const float2*)(bias + gn);
                    const float2 rv = *(const float2*)(resid + (size_t)gm * N + gn);
                    float2 o = {v0 + bv.x + rv.x, v1 + bv.y + rv.y};
                    *(float2*)(outf + (size_t)gm * N + gn) = o;
                } else {
                    const float2 bv = *(const float2*)(bias + gn);
                    float u0 = fmaxf(v0 + bv.x, 0.f);
                    float u1 = fmaxf(v1 + bv.y, 0.f);
                    __nv_bfloat16 h0, l0, h1, l1;
                    split_bf16(u0, h0, l0); split_bf16(u1, h1, l1);
                    __nv_bfloat162 hv = {h0, h1}, lv = {l0, l1};
                    *(__nv_bfloat162*)(ohi + (size_t)gm * N + gn) = hv;
                    *(__nv_bfloat162*)(olo + (size_t)gm * N + gn) = lv;
                }
            }
        }
    }
}

// ---------------- flash attention (fp32 SIMT), outputs split bf16 ---------------
__global__ void __launch_bounds__(256) attn_kernel(
    const float* __restrict__ Qg, const float* __restrict__ Kg,
    const float* __restrict__ Vg,
    __nv_bfloat16* __restrict__ Ohi, __nv_bfloat16* __restrict__ Olo)
{
    __shared__ float Qs[32][65];
    __shared__ float Kst[64][33];
    __shared__ float Vs[32][64];
    __shared__ float Ps[32][33];

    int bh = blockIdx.y;
    int q0 = blockIdx.x * 32;
    const float* qbase = Qg + (size_t)bh * T_ * HS_;
    const float* kbase = Kg + (size_t)bh * T_ * HS_;
    const float* vbase = Vg + (size_t)bh * T_ * HS_;

    int tid = threadIdx.x;
    int r   = tid >> 3;
    int c8  = (tid & 7) * 8;
    int kc0 = (tid & 7) * 4;
    int grow = q0 + r;

    {
        const float* src = qbase + (size_t)grow * HS_ + c8;
        #pragma unroll
        for (int i = 0; i < 8; i++) Qs[r][c8 + i] = src[i];
    }

    float acc[8];
    #pragma unroll
    for (int i = 0; i < 8; i++) acc[i] = 0.f;
    float m_i = -1e30f, l_i = 0.f;

    int ntiles = blockIdx.x + 1;
    for (int kt = 0; kt < ntiles; kt++) {
        __syncthreads();
        {
            const float* ks = kbase + (size_t)(kt * 32 + r) * HS_ + c8;
            const float* vs = vbase + (size_t)(kt * 32 + r) * HS_ + c8;
            #pragma unroll
            for (int i = 0; i < 8; i++) Kst[c8 + i][r] = ks[i];
            #pragma unroll
            for (int i = 0; i < 8; i++) Vs[r][c8 + i] = vs[i];
        }
        __syncthreads();

        float s[4] = {0.f, 0.f, 0.f, 0.f};
        #pragma unroll 8
        for (int d = 0; d < 64; d++) {
            float a = Qs[r][d];
            #pragma unroll
            for (int j = 0; j < 4; j++) s[j] += a * Kst[d][kc0 + j];
        }
        #pragma unroll
        for (int j = 0; j < 4; j++) {
            s[j] *= 0.03125f;
            int gc = kt * 32 + kc0 + j;
            if (gc > grow) s[j] = -1e30f;
        }

        float tm = fmaxf(fmaxf(s[0], s[1]), fmaxf(s[2], s[3]));
        #pragma unroll
        for (int off = 4; off; off >>= 1)
            tm = fmaxf(tm, __shfl_xor_sync(0xffffffffu, tm, off, 8));
        float m_new = fmaxf(m_i, tm);
        float alpha = __expf(m_i - m_new);
        float ps = 0.f;
        #pragma unroll
        for (int j = 0; j < 4; j++) {
            float p = __expf(s[j] - m_new);
            Ps[r][kc0 + j] = p;
            ps += p;
        }
        #pragma unroll
        for (int off = 4; off; off >>= 1)
            ps += __shfl_xor_sync(0xffffffffu, ps, off, 8);
        l_i = l_i * alpha + ps;
        m_i = m_new;
        __syncthreads();

        #pragma unroll
        for (int i = 0; i < 8; i++) acc[i] *= alpha;
        #pragma unroll 4
        for (int j = 0; j < 32; j++) {
            float p = Ps[r][j];
            const float4* vrow = (const float4*)&Vs[j][c8];
            float4 v0 = vrow[0];
            float4 v1 = vrow[1];
            acc[0] += p * v0.x; acc[1] += p * v0.y;
            acc[2] += p * v0.z; acc[3] += p * v0.w;
            acc[4] += p * v1.x; acc[5] += p * v1.y;
            acc[6] += p * v1.z; acc[7] += p * v1.w;
        }
    }

    float inv = 1.0f / l_i;
    int b = bh >> 4, h = bh & 15;
    size_t base = (((size_t)(b * T_ + grow)) * H_ + h) * HS_ + c8;
    __nv_bfloat16 hv[8], lv[8];
    #pragma unroll
    for (int i = 0; i < 8; i++) split_bf16(acc[i] * inv, hv[i], lv[i]);
    *(uint4*)(Ohi + base) = *(uint4*)hv;
    *(uint4*)(Olo + base) = *(uint4*)lv;
}

// ---------------- launch --------------------------------------------------------
extern "C" void kernel_launch(void* const* d_in, const int* in_sizes, int n_in,
                              void* d_out, int out_size)
{
    const float* x    = (const float*)d_in[0];
    const float* Wq   = (const float*)d_in[1];
    const float* Wk   = (const float*)d_in[2];
    const float* Wv   = (const float*)d_in[3];
    const float* Wo   = (const float*)d_in[4];
    const float* bo   = (const float*)d_in[5];
    const float* W1   = (const float*)d_in[6];
    const float* b1   = (const float*)d_in[7];
    const float* W2   = (const float*)d_in[8];
    const float* b2   = (const float*)d_in[9];
    const float* ln1w = (const float*)d_in[10];
    const float* ln1b = (const float*)d_in[11];
    const float* ln2w = (const float*)d_in[12];
    const float* ln2b = (const float*)d_in[13];
    float* out = (float*)d_out;

    __nv_bfloat16 *hhi, *hlo, *athi, *atlo, *f1hi, *f1lo;
    __nv_bfloat16 *wqkvh, *wqkvl, *woh, *wol, *w1h, *w1l, *w2h, *w2l;
    float *pq, *pk, *pv;
    cudaGetSymbolAddress((void**)&hhi,   g_h_hi);
    cudaGetSymbolAddress((void**)&hlo,   g_h_lo);
    cudaGetSymbolAddress((void**)&athi,  g_at_hi);
    cudaGetSymbolAddress((void**)&atlo,  g_at_lo);
    cudaGetSymbolAddress((void**)&f1hi,  g_f1_hi);
    cudaGetSymbolAddress((void**)&f1lo,  g_f1_lo);
    cudaGetSymbolAddress((void**)&pq,    g_q);
    cudaGetSymbolAddress((void**)&pk,    g_k);
    cudaGetSymbolAddress((void**)&pv,    g_v);
    cudaGetSymbolAddress((void**)&wqkvh, g_wqkv_hi);
    cudaGetSymbolAddress((void**)&wqkvl, g_wqkv_lo);
    cudaGetSymbolAddress((void**)&woh,   g_wo_hi);
    cudaGetSymbolAddress((void**)&wol,   g_wo_lo);
    cudaGetSymbolAddress((void**)&w1h,   g_w1_hi);
    cudaGetSymbolAddress((void**)&w1l,   g_w1_lo);
    cudaGetSymbolAddress((void**)&w2h,   g_w2_hi);
    cudaGetSymbolAddress((void**)&w2l,   g_w2_lo);

    cudaFuncSetAttribute(tgemm_kernel<0>, cudaFuncAttributeMaxDynamicSharedMemorySize, SMEM_GEMM);
    cudaFuncSetAttribute(tgemm_kernel<1>, cudaFuncAttributeMaxDynamicSharedMemorySize, SMEM_GEMM);
    cudaFuncSetAttribute(tgemm_kernel<2>, cudaFuncAttributeMaxDynamicSharedMemorySize, SMEM_GEMM);

    dim3 tb(32, 8);

    // weight prep (transpose + split)
    trans_qkv_kernel<<<dim3(2, 32, 48), tb>>>(Wq, Wk, Wv, wqkvh, wqkvl);
    trans_split_kernel<<<dim3(32, 32), tb>>>(Wo, E_, E_, woh, wol);
    trans_split_kernel<<<dim3(128, 32), tb>>>(W1, E_, FF_, w1h, w1l);
    trans_split_kernel<<<dim3(32, 128), tb>>>(W2, FF_, E_, w2h, w2l);

    // h = LN1(x) -> split bf16
    ln_kernel<<<M_, 256>>>(x, ln1w, ln1b, hhi, hlo);

    // q,k,v = h @ Wqkv (scatter fp32)
    tgemm_kernel<0><<<dim3(3*E_/128, M_/128), 256, SMEM_GEMM>>>(
        hhi, hlo, wqkvh, wqkvl, M_, 3*E_, E_,
        nullptr, nullptr, nullptr, nullptr, nullptr, pq, pk, pv);

    // attention -> split bf16 [B,T,H,HS]
    attn_kernel<<<dim3(T_/32, B_*H_), 256>>>(pq, pk, pv, athi, atlo);

    // x1 = x + attn @ Wo + bo  (fp32, into d_out)
    tgemm_kernel<1><<<dim3(E_/128, M_/128), 256, SMEM_GEMM>>>(
        athi, atlo, woh, wol, M_, E_, E_,
        bo, x, out, nullptr, nullptr, nullptr, nullptr, nullptr);

    // h2 = LN2(x1) -> split bf16
    ln_kernel<<<M_, 256>>>(out, ln2w, ln2b, hhi, hlo);

    // f1 = relu(h2 @ W1 + b1) -> split bf16
    tgemm_kernel<2><<<dim3(FF_/128, M_/128), 256, SMEM_GEMM>>>(
        hhi, hlo, w1h, w1l, M_, FF_, E_,
        b1, nullptr, nullptr, f1hi, f1lo, nullptr, nullptr, nullptr);

    // out = x1 + f1 @ W2 + b2
    tgemm_kernel<1><<<dim3(E_/128, M_/128), 256, SMEM_GEMM>>>(
        f1hi, f1lo, w2h, w2l, M_, E_, FF_,
        b2, out, out, nullptr, nullptr, nullptr, nullptr, nullptr);
}

// round 11
// speedup vs baseline: 2.5585x; 1.0001x over previous
#include <cuda_runtime.h>
#include <cuda_bf16.h>
#include <cstdint>
#include <cstddef>

// Problem constants
#define B_  64
#define T_  320
#define E_  1024
#define H_  16
#define HS_ 64
#define M_  (B_*T_)      // 20480 tokens
#define FF_ (4*E_)       // 4096

// ===================== baseline-PTX helpers (no 'a'-arch features!) ============
__device__ __forceinline__ uint32_t smem_to_u32(const void* p) {
    uint32_t a;
    asm("{ .reg .u64 t; cvta.to.shared.u64 t, %1; cvt.u32.u64 %0, t; }" : "=r"(a) : "l"(p));
    return a;
}
__device__ __forceinline__ void cp16(uint32_t s, const void* g) {
    asm volatile("cp.async.cg.shared.global [%0], [%1], 16;" :: "r"(s), "l"(g));
}
#define CP_COMMIT() asm volatile("cp.async.commit_group;" ::: "memory")
#define CP_WAIT1()  asm volatile("cp.async.wait_group 1;"  ::: "memory")

__device__ __forceinline__ void ldsm4(uint32_t* r, uint32_t addr) {
    asm volatile("ldmatrix.sync.aligned.m8n8.x4.shared.b16 {%0,%1,%2,%3}, [%4];"
        : "=r"(r[0]), "=r"(r[1]), "=r"(r[2]), "=r"(r[3]) : "r"(addr));
}
__device__ __forceinline__ void mma16816(float* c, const uint32_t* a,
                                         uint32_t b0, uint32_t b1) {
    asm volatile(
        "mma.sync.aligned.m16n8k16.row.col.f32.bf16.bf16.f32 "
        "{%0,%1,%2,%3},{%4,%5,%6,%7},{%8,%9},{%0,%1,%2,%3};"
        : "+f"(c[0]), "+f"(c[1]), "+f"(c[2]), "+f"(c[3])
        : "r"(a[0]), "r"(a[1]), "r"(a[2]), "r"(a[3]), "r"(b0), "r"(b1));
}

// ===================== device scratch (no allocations allowed) ==================
__device__ __nv_bfloat16 g_h_hi   [(size_t)M_*E_];
__device__ __nv_bfloat16 g_h_lo   [(size_t)M_*E_];
__device__ __nv_bfloat16 g_at_hi  [(size_t)M_*E_];
__device__ __nv_bfloat16 g_at_lo  [(size_t)M_*E_];
__device__ __nv_bfloat16 g_f1_hi  [(size_t)M_*FF_];
__device__ __nv_bfloat16 g_f1_lo  [(size_t)M_*FF_];
__device__ float         g_q      [(size_t)M_*E_];
__device__ float         g_k      [(size_t)M_*E_];
__device__ float         g_v      [(size_t)M_*E_];
__device__ __nv_bfloat16 g_wqkv_hi[(size_t)3*E_*E_];   // [N=3E, K=E]
__device__ __nv_bfloat16 g_wqkv_lo[(size_t)3*E_*E_];
__device__ __nv_bfloat16 g_wo_hi  [(size_t)E_*E_];     // [N=E, K=E]
__device__ __nv_bfloat16 g_wo_lo  [(size_t)E_*E_];
__device__ __nv_bfloat16 g_w1_hi  [(size_t)FF_*E_];    // [N=4E, K=E]
__device__ __nv_bfloat16 g_w1_lo  [(size_t)FF_*E_];
__device__ __nv_bfloat16 g_w2_hi  [(size_t)E_*FF_];    // [N=E, K=4E]
__device__ __nv_bfloat16 g_w2_lo  [(size_t)E_*FF_];

__device__ __forceinline__ void split_bf16(float v, __nv_bfloat16& hi, __nv_bfloat16& lo) {
    hi = __float2bfloat16(v);
    lo = __float2bfloat16(v - __bfloat162float(hi));
}

// ============ weight prep: transpose fp32 [K,N] -> bf16 hi/lo [N,K] =============
__global__ void trans_split_kernel(const float* __restrict__ in, int K, int N,
                                   __nv_bfloat16* __restrict__ ohi,
                                   __nv_bfloat16* __restrict__ olo)
{
    __shared__ float t[32][33];
    int nb = blockIdx.x * 32, kb = blockIdx.y * 32;
    int tx = threadIdx.x, ty = threadIdx.y;          // 32 x 8
    #pragma unroll
    for (int j = 0; j < 4; j++)
        t[ty + j*8][tx] = in[(size_t)(kb + ty + j*8) * N + nb + tx];
    __syncthreads();
    #pragma unroll
    for (int j = 0; j < 4; j++) {
        float v = t[tx][ty + j*8];
        int orow = nb + ty + j*8, ocol = kb + tx;
        __nv_bfloat16 hi, lo; split_bf16(v, hi, lo);
        ohi[(size_t)orow * K + ocol] = hi;
        olo[(size_t)orow * K + ocol] = lo;
    }
}

// Wq/Wk/Wv (H,E,HS) -> [3E rows, E cols] transposed split
__global__ void trans_qkv_kernel(const float* __restrict__ Wq,
                                 const float* __restrict__ Wk,
                                 const float* __restrict__ Wv,
                                 __nv_bfloat16* __restrict__ ohi,
                                 __nv_bfloat16* __restrict__ olo)
{
    __shared__ float t[32][33];
    int z = blockIdx.z;                               // which*16 + h
    const float* W = (z < 16) ? Wq : (z < 32) ? Wk : Wv;
    const float* in = W + (size_t)(z & 15) * E_ * HS_;  // [E, 64]
    int nb = blockIdx.x * 32, kb = blockIdx.y * 32;
    int tx = threadIdx.x, ty = threadIdx.y;
    #pragma unroll
    for (int j = 0; j < 4; j++)
        t[ty + j*8][tx] = in[(size_t)(kb + ty + j*8) * HS_ + nb + tx];
    __syncthreads();
    #pragma unroll
    for (int j = 0; j < 4; j++) {
        float v = t[tx][ty + j*8];
        int orow = z * 64 + nb + ty + j*8;            // output N row
        int ocol = kb + tx;                           // K
        __nv_bfloat16 hi, lo; split_bf16(v, hi, lo);
        ohi[(size_t)orow * E_ + ocol] = hi;
        olo[(size_t)orow * E_ + ocol] = lo;
    }
}

// ================= layernorm -> split bf16 hi/lo =================================
__global__ void __launch_bounds__(256) ln_kernel(const float* __restrict__ x,
                                                 const float* __restrict__ w,
                                                 const float* __restrict__ b,
                                                 __nv_bfloat16* __restrict__ ohi,
                                                 __nv_bfloat16* __restrict__ olo)
{
    int row = blockIdx.x;
    int t = threadIdx.x;
    float4 v = ((const float4*)(x + (size_t)row * E_))[t];
    float s  = v.x + v.y + v.z + v.w;
    float sq = v.x*v.x + v.y*v.y + v.z*v.z + v.w*v.w;
    #pragma unroll
    for (int off = 16; off; off >>= 1) {
        s  += __shfl_xor_sync(0xffffffffu, s,  off);
        sq += __shfl_xor_sync(0xffffffffu, sq, off);
    }
    __shared__ float ss[8], ssq[8];
    int warp = t >> 5, lane = t & 31;
    if (lane == 0) { ss[warp] = s; ssq[warp] = sq; }
    __syncthreads();
    float tot = 0.f, totq = 0.f;
    #pragma unroll
    for (int i = 0; i < 8; i++) { tot += ss[i]; totq += ssq[i]; }
    float mu  = tot * (1.0f / E_);
    float var = totq * (1.0f / E_) - mu * mu;
    float rs  = rsqrtf(var + 1e-5f);
    float4 w4 = ((const float4*)w)[t];
    float4 b4 = ((const float4*)b)[t];
    float r0 = (v.x - mu) * rs * w4.x + b4.x;
    float r1 = (v.y - mu) * rs * w4.y + b4.y;
    float r2 = (v.z - mu) * rs * w4.z + b4.z;
    float r3 = (v.w - mu) * rs * w4.w + b4.w;
    __nv_bfloat16 h0,l0,h1,l1,h2,l2,h3,l3;
    split_bf16(r0,h0,l0); split_bf16(r1,h1,l1); split_bf16(r2,h2,l2); split_bf16(r3,h3,l3);
    __nv_bfloat162 hh0 = {h0, h1}, hh1 = {h2, h3};
    __nv_bfloat162 ll0 = {l0, l1}, ll1 = {l2, l3};
    uint2 hp = { *(uint32_t*)&hh0, *(uint32_t*)&hh1 };
    uint2 lp = { *(uint32_t*)&ll0, *(uint32_t*)&ll1 };
    ((uint2*)(ohi + (size_t)row * E_))[t] = hp;
    ((uint2*)(olo + (size_t)row * E_))[t] = lp;
}

// ================= mma.sync split-bf16 GEMM =====================================
// C[M,N] = A[M,K] * B[N,K]^T. 128x128 tile, K-chunk 32, 8 warps (2x4),
// warp tile 64x32 = 4x4 m16n8k16 atoms, 3-stage cp.async pipeline.
// Split-bf16: acc += Ahi*Bhi + Ahi*Blo + Alo*Bhi  (fp32 register accum).
// EPI 0: scatter fp32 to q/k/v   EPI 1: fp32 out = acc+bias+resid
// EPI 2: bf16 hi/lo out = split(relu(acc+bias))

#define ST_HALF  8192                  // 128 rows x 64B
#define STAGE_B  (4*ST_HALF)           // Ahi,Alo,Bhi,Blo
#define NSTAGE   3
#define SMEM_GEMM (NSTAGE*STAGE_B)     // 96 KB

// XOR swizzle: row pitch 64B, chunk index cb (0..3, 16B units)
__device__ __forceinline__ uint32_t swz(int row, int cb) {
    return (uint32_t)((row << 6) + ((cb ^ ((row >> 1) & 3)) << 4));
}

template<int EPI>
__global__ void __launch_bounds__(256) tgemm_kernel(
    const __nv_bfloat16* __restrict__ Ahi, const __nv_bfloat16* __restrict__ Alo,
    const __nv_bfloat16* __restrict__ Bhi, const __nv_bfloat16* __restrict__ Blo,
    int M, int N, int K,
    const float* __restrict__ bias, const float* __restrict__ resid,
    float* __restrict__ outf,
    __nv_bfloat16* __restrict__ ohi, __nv_bfloat16* __restrict__ olo,
    float* __restrict__ qo, float* __restrict__ ko, float* __restrict__ vo)
{
    extern __shared__ char smem[];
    uint32_t sb = smem_to_u32(smem);
    int tid  = threadIdx.x;
    int lane = tid & 31, wid = tid >> 5;
    int bm = blockIdx.y, bn = blockIdx.x;
    int wm = wid >> 2, wn = wid & 3;

    const char* pAhi = (const char*)Ahi;
    const char* pAlo = (const char*)Alo;
    const char* pBhi = (const char*)Bhi;
    const char* pBlo = (const char*)Blo;
    const int K2 = K * 2;                       // bytes per K-row
    const size_t aBase = (size_t)(bm * 128) * K2;
    const size_t bBase = (size_t)(bn * 128) * K2;
    const int nch = K >> 5;                     // K-chunks of 32

    // per-thread load coords: 2 x 16B chunks per operand-half per stage
    int rr0 = tid >> 2,        cb0 = tid & 3;          // idx = tid
    int rr1 = (tid + 256) >> 2, cb1 = tid & 3;         // idx = tid+256

    // ldmatrix coords
    int a_row  = wm * 64 + (lane & 15);
    int a_cbo  = lane >> 4;                     // 0/1
    int bg = lane >> 3, br = lane & 7;
    int b_row  = wn * 32 + ((bg >> 1) << 3) + br;
    int b_cbo  = bg & 1;

    float acc[4][4][4];
    #pragma unroll
    for (int a = 0; a < 4; a++)
        #pragma unroll
        for (int nb = 0; nb < 4; nb++)
            #pragma unroll
            for (int i = 0; i < 4; i++) acc[a][nb][i] = 0.f;

    // ---- loader lambda-ish macro ----
    #define LOAD_STAGE(sidx, kb) do {                                              \
        uint32_t s_ = sb + (uint32_t)(sidx) * STAGE_B;                              \
        uint32_t o0 = swz(rr0, cb0), o1 = swz(rr1, cb1);                            \
        size_t ga0 = aBase + (size_t)rr0 * K2 + (kb) + cb0 * 16;                    \
        size_t ga1 = aBase + (size_t)rr1 * K2 + (kb) + cb1 * 16;                    \
        size_t gb0 = bBase + (size_t)rr0 * K2 + (kb) + cb0 * 16;                    \
        size_t gb1 = bBase + (size_t)rr1 * K2 + (kb) + cb1 * 16;                    \
        cp16(s_ + o0,             pAhi + ga0);                                      \
        cp16(s_ + o1,             pAhi + ga1);                                      \
        cp16(s_ + ST_HALF + o0,   pAlo + ga0);                                      \
        cp16(s_ + ST_HALF + o1,   pAlo + ga1);                                      \
        cp16(s_ + 2*ST_HALF + o0, pBhi + gb0);                                      \
        cp16(s_ + 2*ST_HALF + o1, pBhi + gb1);                                      \
        cp16(s_ + 3*ST_HALF + o0, pBlo + gb0);                                      \
        cp16(s_ + 3*ST_HALF + o1, pBlo + gb1);                                      \
    } while (0)

    // prologue: 2 stages in flight
    LOAD_STAGE(0, 0);   CP_COMMIT();
    LOAD_STAGE(1, 64);  CP_COMMIT();

    int sidx = 0;
    for (int c = 0; c < nch; c++) {
        CP_WAIT1();
        __syncthreads();
        // prefetch chunk c+2
        if (c + 2 < nch) {
            int nsi = sidx + 2; if (nsi >= NSTAGE) nsi -= NSTAGE;
            LOAD_STAGE(nsi, (size_t)(c + 2) * 64);
        }
        CP_COMMIT();

        uint32_t s = sb + (uint32_t)sidx * STAGE_B;
        #pragma unroll
        for (int ks = 0; ks < 2; ks++) {
            uint32_t ahi[4][4], alo[4][4];
            int acb = ks * 2 + a_cbo;
            #pragma unroll
            for (int a = 0; a < 4; a++) {
                uint32_t ad = s + swz(a_row + a * 16, acb);
                ldsm4(ahi[a], ad);
                ldsm4(alo[a], ad + ST_HALF);
            }
            uint32_t bhi[2][4], blo[2][4];
            int bcb = ks * 2 + b_cbo;
            #pragma unroll
            for (int p = 0; p < 2; p++) {
                uint32_t bd = s + 2 * ST_HALF + swz(b_row + p * 16, bcb);
                ldsm4(bhi[p], bd);
                ldsm4(blo[p], bd + ST_HALF);
            }
            #pragma unroll
            for (int a = 0; a < 4; a++)
                #pragma unroll
                for (int p = 0; p < 2; p++)
                    #pragma unroll
                    for (int h = 0; h < 2; h++) {
                        int nb = p * 2 + h;
                        mma16816(acc[a][nb], ahi[a], bhi[p][2*h], bhi[p][2*h+1]);
                        mma16816(acc[a][nb], ahi[a], blo[p][2*h], blo[p][2*h+1]);
                        mma16816(acc[a][nb], alo[a], bhi[p][2*h], bhi[p][2*h+1]);
                    }
        }
        sidx++; if (sidx >= NSTAGE) sidx = 0;
    }
    #undef LOAD_STAGE

    // ---- epilogue: C fragment (m=lane/4 [+8], n=2*(lane%4)+{0,1}) --------------
    int erow0 = bm * 128 + wm * 64 + (lane >> 2);
    int ecol0 = bn * 128 + wn * 32 + 2 * (lane & 3);

    #pragma unroll
    for (int a = 0; a < 4; a++) {
        #pragma unroll
        for (int nb = 0; nb < 4; nb++) {
            int gn = ecol0 + nb * 8;
            #pragma unroll
            for (int half = 0; half < 2; half++) {
                int gm = erow0 + a * 16 + half * 8;
                float v0 = acc[a][nb][half * 2 + 0];
                float v1 = acc[a][nb][half * 2 + 1];
                if (EPI == 0) {
                    int which = gn >> 10;
                    int w = gn & (E_ - 1);
                    int hh = w >> 6, dd = w & 63;
                    int bk = gm / T_, tt = gm - bk * T_;
                    float* dst = (which == 0) ? qo : (which == 1) ? ko : vo;
                    float2 o = {v0, v1};
                    *(float2*)(dst + (((size_t)(bk * H_ + hh)) * T_ + tt) * HS_ + dd) = o;
                } else if (EPI == 1) {
                    const float2 bv = *(const float2*)(bias + gn);
                    const float2 rv = *(const float2*)(resid + (size_t)gm * N + gn);
                    float2 o = {v0 + bv.x + rv.x, v1 + bv.y + rv.y};
                    *(float2*)(outf + (size_t)gm * N + gn) = o;
                } else {
                    const float2 bv = *(const float2*)(bias + gn);
                    float u0 = fmaxf(v0 + bv.x, 0.f);
                    float u1 = fmaxf(v1 + bv.y, 0.f);
                    __nv_bfloat16 h0, l0, h1, l1;
                    split_bf16(u0, h0, l0); split_bf16(u1, h1, l1);
                    __nv_bfloat162 hv = {h0, h1}, lv = {l0, l1};
                    *(__nv_bfloat162*)(ohi + (size_t)gm * N + gn) = hv;
                    *(__nv_bfloat162*)(olo + (size_t)gm * N + gn) = lv;
                }
            }
        }
    }
}

// ---------------- flash attention (fp32 SIMT), outputs split bf16 ---------------
__global__ void __launch_bounds__(256) attn_kernel(
    const float* __restrict__ Qg, const float* __restrict__ Kg,
    const float* __restrict__ Vg,
    __nv_bfloat16* __restrict__ Ohi, __nv_bfloat16* __restrict__ Olo)
{
    __shared__ float Qs[32][65];
    __shared__ float Kst[64][33];
    __shared__ float Vs[32][64];
    __shared__ float Ps[32][33];

    int bh = blockIdx.y;
    int q0 = blockIdx.x * 32;
    const float* qbase = Qg + (size_t)bh * T_ * HS_;
    const float* kbase = Kg + (size_t)bh * T_ * HS_;
    const float* vbase = Vg + (size_t)bh * T_ * HS_;

    int tid = threadIdx.x;
    int r   = tid >> 3;
    int c8  = (tid & 7) * 8;
    int kc0 = (tid & 7) * 4;
    int grow = q0 + r;

    {
        const float* src = qbase + (size_t)grow * HS_ + c8;
        #pragma unroll
        for (int i = 0; i < 8; i++) Qs[r][c8 + i] = src[i];
    }

    float acc[8];
    #pragma unroll
    for (int i = 0; i < 8; i++) acc[i] = 0.f;
    float m_i = -1e30f, l_i = 0.f;

    int ntiles = blockIdx.x + 1;
    for (int kt = 0; kt < ntiles; kt++) {
        __syncthreads();
        {
            const float* ks = kbase + (size_t)(kt * 32 + r) * HS_ + c8;
            const float* vs = vbase + (size_t)(kt * 32 + r) * HS_ + c8;
            #pragma unroll
            for (int i = 0; i < 8; i++) Kst[c8 + i][r] = ks[i];
            #pragma unroll
            for (int i = 0; i < 8; i++) Vs[r][c8 + i] = vs[i];
        }
        __syncthreads();

        float s[4] = {0.f, 0.f, 0.f, 0.f};
        #pragma unroll 8
        for (int d = 0; d < 64; d++) {
            float a = Qs[r][d];
            #pragma unroll
            for (int j = 0; j < 4; j++) s[j] += a * Kst[d][kc0 + j];
        }
        #pragma unroll
        for (int j = 0; j < 4; j++) {
            s[j] *= 0.03125f;
            int gc = kt * 32 + kc0 + j;
            if (gc > grow) s[j] = -1e30f;
        }

        float tm = fmaxf(fmaxf(s[0], s[1]), fmaxf(s[2], s[3]));
        #pragma unroll
        for (int off = 4; off; off >>= 1)
            tm = fmaxf(tm, __shfl_xor_sync(0xffffffffu, tm, off, 8));
        float m_new = fmaxf(m_i, tm);
        float alpha = __expf(m_i - m_new);
        float ps = 0.f;
        #pragma unroll
        for (int j = 0; j < 4; j++) {
            float p = __expf(s[j] - m_new);
            Ps[r][kc0 + j] = p;
            ps += p;
        }
        #pragma unroll
        for (int off = 4; off; off >>= 1)
            ps += __shfl_xor_sync(0xffffffffu, ps, off, 8);
        l_i = l_i * alpha + ps;
        m_i = m_new;
        __syncthreads();

        #pragma unroll
        for (int i = 0; i < 8; i++) acc[i] *= alpha;
        #pragma unroll 4
        for (int j = 0; j < 32; j++) {
            float p = Ps[r][j];
            const float4* vrow = (const float4*)&Vs[j][c8];
            float4 v0 = vrow[0];
            float4 v1 = vrow[1];
            acc[0] += p * v0.x; acc[1] += p * v0.y;
            acc[2] += p * v0.z; acc[3] += p * v0.w;
            acc[4] += p * v1.x; acc[5] += p * v1.y;
            acc[6] += p * v1.z; acc[7] += p * v1.w;
        }
    }

    float inv = 1.0f / l_i;
    int b = bh >> 4, h = bh & 15;
    size_t base = (((size_t)(b * T_ + grow)) * H_ + h) * HS_ + c8;
    __nv_bfloat16 hv[8], lv[8];
    #pragma unroll
    for (int i = 0; i < 8; i++) split_bf16(acc[i] * inv, hv[i], lv[i]);
    *(uint4*)(Ohi + base) = *(uint4*)hv;
    *(uint4*)(Olo + base) = *(uint4*)lv;
}

// ---------------- launch --------------------------------------------------------
extern "C" void kernel_launch(void* const* d_in, const int* in_sizes, int n_in,
                              void* d_out, int out_size)
{
    const float* x    = (const float*)d_in[0];
    const float* Wq   = (const float*)d_in[1];
    const float* Wk   = (const float*)d_in[2];
    const float* Wv   = (const float*)d_in[3];
    const float* Wo   = (const float*)d_in[4];
    const float* bo   = (const float*)d_in[5];
    const float* W1   = (const float*)d_in[6];
    const float* b1   = (const float*)d_in[7];
    const float* W2   = (const float*)d_in[8];
    const float* b2   = (const float*)d_in[9];
    const float* ln1w = (const float*)d_in[10];
    const float* ln1b = (const float*)d_in[11];
    const float* ln2w = (const float*)d_in[12];
    const float* ln2b = (const float*)d_in[13];
    float* out = (float*)d_out;

    __nv_bfloat16 *hhi, *hlo, *athi, *atlo, *f1hi, *f1lo;
    __nv_bfloat16 *wqkvh, *wqkvl, *woh, *wol, *w1h, *w1l, *w2h, *w2l;
    float *pq, *pk, *pv;
    cudaGetSymbolAddress((void**)&hhi,   g_h_hi);
    cudaGetSymbolAddress((void**)&hlo,   g_h_lo);
    cudaGetSymbolAddress((void**)&athi,  g_at_hi);
    cudaGetSymbolAddress((void**)&atlo,  g_at_lo);
    cudaGetSymbolAddress((void**)&f1hi,  g_f1_hi);
    cudaGetSymbolAddress((void**)&f1lo,  g_f1_lo);
    cudaGetSymbolAddress((void**)&pq,    g_q);
    cudaGetSymbolAddress((void**)&pk,    g_k);
    cudaGetSymbolAddress((void**)&pv,    g_v);
    cudaGetSymbolAddress((void**)&wqkvh, g_wqkv_hi);
    cudaGetSymbolAddress((void**)&wqkvl, g_wqkv_lo);
    cudaGetSymbolAddress((void**)&woh,   g_wo_hi);
    cudaGetSymbolAddress((void**)&wol,   g_wo_lo);
    cudaGetSymbolAddress((void**)&w1h,   g_w1_hi);
    cudaGetSymbolAddress((void**)&w1l,   g_w1_lo);
    cudaGetSymbolAddress((void**)&w2h,   g_w2_hi);
    cudaGetSymbolAddress((void**)&w2l,   g_w2_lo);

    cudaFuncSetAttribute(tgemm_kernel<0>, cudaFuncAttributeMaxDynamicSharedMemorySize, SMEM_GEMM);
    cudaFuncSetAttribute(tgemm_kernel<1>, cudaFuncAttributeMaxDynamicSharedMemorySize, SMEM_GEMM);
    cudaFuncSetAttribute(tgemm_kernel<2>, cudaFuncAttributeMaxDynamicSharedMemorySize, SMEM_GEMM);

    dim3 tb(32, 8);

    // weight prep (transpose + split)
    trans_qkv_kernel<<<dim3(2, 32, 48), tb>>>(Wq, Wk, Wv, wqkvh, wqkvl);
    trans_split_kernel<<<dim3(32, 32), tb>>>(Wo, E_, E_, woh, wol);
    trans_split_kernel<<<dim3(128, 32), tb>>>(W1, E_, FF_, w1h, w1l);
    trans_split_kernel<<<dim3(32, 128), tb>>>(W2, FF_, E_, w2h, w2l);

    // h = LN1(x) -> split bf16
    ln_kernel<<<M_, 256>>>(x, ln1w, ln1b, hhi, hlo);

    // q,k,v = h @ Wqkv (scatter fp32)
    tgemm_kernel<0><<<dim3(3*E_/128, M_/128), 256, SMEM_GEMM>>>(
        hhi, hlo, wqkvh, wqkvl, M_, 3*E_, E_,
        nullptr, nullptr, nullptr, nullptr, nullptr, pq, pk, pv);

    // attention -> split bf16 [B,T,H,HS]
    attn_kernel<<<dim3(T_/32, B_*H_), 256>>>(pq, pk, pv, athi, atlo);

    // x1 = x + attn @ Wo + bo  (fp32, into d_out)
    tgemm_kernel<1><<<dim3(E_/128, M_/128), 256, SMEM_GEMM>>>(
        athi, atlo, woh, wol, M_, E_, E_,
        bo, x, out, nullptr, nullptr, nullptr, nullptr, nullptr);

    // h2 = LN2(x1) -> split bf16
    ln_kernel<<<M_, 256>>>(out, ln2w, ln2b, hhi, hlo);

    // f1 = relu(h2 @ W1 + b1) -> split bf16
    tgemm_kernel<2><<<dim3(FF_/128, M_/128), 256, SMEM_GEMM>>>(
        hhi, hlo, w1h, w1l, M_, FF_, E_,
        b1, nullptr, nullptr, f1hi, f1lo, nullptr, nullptr, nullptr);

    // out = x1 + f1 @ W2 + b2
    tgemm_kernel<1><<<dim3(E_/128, M_/128), 256, SMEM_GEMM>>>(
        f1hi, f1lo, w2h, w2l, M_, E_, FF_,
        b2, out, out, nullptr, nullptr, nullptr, nullptr, nullptr);
}

// round 12
// speedup vs baseline: 5.3202x; 2.0794x over previous
#include <cuda_runtime.h>
#include <cuda_fp16.h>
#include <cstdint>
#include <cstddef>

// Problem constants
#define B_  64
#define T_  320
#define E_  1024
#define H_  16
#define HS_ 64
#define M_  (B_*T_)      // 20480 tokens
#define FF_ (4*E_)       // 4096

// ===================== baseline-PTX helpers (no 'a'-arch features) =============
__device__ __forceinline__ uint32_t smem_to_u32(const void* p) {
    uint32_t a;
    asm("{ .reg .u64 t; cvta.to.shared.u64 t, %1; cvt.u32.u64 %0, t; }" : "=r"(a) : "l"(p));
    return a;
}
__device__ __forceinline__ void cp16(uint32_t s, const void* g) {
    asm volatile("cp.async.cg.shared.global [%0], [%1], 16;" :: "r"(s), "l"(g));
}
#define CP_COMMIT() asm volatile("cp.async.commit_group;" ::: "memory")
#define CP_WAIT0()  asm volatile("cp.async.wait_group 0;"  ::: "memory")
#define CP_WAIT1()  asm volatile("cp.async.wait_group 1;"  ::: "memory")
#define CP_WAIT2()  asm volatile("cp.async.wait_group 2;"  ::: "memory")

__device__ __forceinline__ void ldsm4(uint32_t* r, uint32_t addr) {
    asm volatile("ldmatrix.sync.aligned.m8n8.x4.shared.b16 {%0,%1,%2,%3}, [%4];"
        : "=r"(r[0]), "=r"(r[1]), "=r"(r[2]), "=r"(r[3]) : "r"(addr));
}
__device__ __forceinline__ void ldsm4t(uint32_t* r, uint32_t addr) {
    asm volatile("ldmatrix.sync.aligned.m8n8.x4.trans.shared.b16 {%0,%1,%2,%3}, [%4];"
        : "=r"(r[0]), "=r"(r[1]), "=r"(r[2]), "=r"(r[3]) : "r"(addr));
}
// fp16 MMA, fp32 accumulate
__device__ __forceinline__ void mma16816(float* c, const uint32_t* a,
                                         uint32_t b0, uint32_t b1) {
    asm volatile(
        "mma.sync.aligned.m16n8k16.row.col.f32.f16.f16.f32 "
        "{%0,%1,%2,%3},{%4,%5,%6,%7},{%8,%9},{%0,%1,%2,%3};"
        : "+f"(c[0]), "+f"(c[1]), "+f"(c[2]), "+f"(c[3])
        : "r"(a[0]), "r"(a[1]), "r"(a[2]), "r"(a[3]), "r"(b0), "r"(b1));
}
__device__ __forceinline__ uint32_t f22u(float a, float b) {
    __half2 h = __float22half2_rn(make_float2(a, b));
    return *(uint32_t*)&h;
}

// ===================== device scratch (no allocations allowed) ==================
__device__ __half g_h   [(size_t)M_*E_];     // LN output (single fp16)
__device__ __half g_at  [(size_t)M_*E_];     // attention out [B,T,H,HS]
__device__ __half g_f1  [(size_t)M_*FF_];    // relu(h2@W1+b1)
__device__ __half g_q   [(size_t)M_*E_];     // [B,H,T,HS] fp16
__device__ __half g_k   [(size_t)M_*E_];
__device__ __half g_v   [(size_t)M_*E_];
__device__ __half g_wqkv_hi[(size_t)3*E_*E_];  // [N=3E, K=E]
__device__ __half g_wqkv_lo[(size_t)3*E_*E_];
__device__ __half g_wo_hi  [(size_t)E_*E_];
__device__ __half g_wo_lo  [(size_t)E_*E_];
__device__ __half g_w1_hi  [(size_t)FF_*E_];
__device__ __half g_w1_lo  [(size_t)FF_*E_];
__device__ __half g_w2_hi  [(size_t)E_*FF_];
__device__ __half g_w2_lo  [(size_t)E_*FF_];

__device__ __forceinline__ void split_h(float v, __half& hi, __half& lo) {
    hi = __float2half_rn(v);
    lo = __float2half_rn(v - __half2float(hi));
}

// ============ weight prep: transpose fp32 [K,N] -> fp16 hi/lo [N,K] =============
__global__ void trans_split_kernel(const float* __restrict__ in, int K, int N,
                                   __half* __restrict__ ohi, __half* __restrict__ olo)
{
    __shared__ float t[32][33];
    int nb = blockIdx.x * 32, kb = blockIdx.y * 32;
    int tx = threadIdx.x, ty = threadIdx.y;          // 32 x 8
    #pragma unroll
    for (int j = 0; j < 4; j++)
        t[ty + j*8][tx] = in[(size_t)(kb + ty + j*8) * N + nb + tx];
    __syncthreads();
    #pragma unroll
    for (int j = 0; j < 4; j++) {
        float v = t[tx][ty + j*8];
        int orow = nb + ty + j*8, ocol = kb + tx;
        __half hi, lo; split_h(v, hi, lo);
        ohi[(size_t)orow * K + ocol] = hi;
        olo[(size_t)orow * K + ocol] = lo;
    }
}

// Wq/Wk/Wv (H,E,HS) -> [3E rows, E cols] transposed split
__global__ void trans_qkv_kernel(const float* __restrict__ Wq,
                                 const float* __restrict__ Wk,
                                 const float* __restrict__ Wv,
                                 __half* __restrict__ ohi, __half* __restrict__ olo)
{
    __shared__ float t[32][33];
    int z = blockIdx.z;
    const float* W = (z < 16) ? Wq : (z < 32) ? Wk : Wv;
    const float* in = W + (size_t)(z & 15) * E_ * HS_;
    int nb = blockIdx.x * 32, kb = blockIdx.y * 32;
    int tx = threadIdx.x, ty = threadIdx.y;
    #pragma unroll
    for (int j = 0; j < 4; j++)
        t[ty + j*8][tx] = in[(size_t)(kb + ty + j*8) * HS_ + nb + tx];
    __syncthreads();
    #pragma unroll
    for (int j = 0; j < 4; j++) {
        float v = t[tx][ty + j*8];
        int orow = z * 64 + nb + ty + j*8;
        int ocol = kb + tx;
        __half hi, lo; split_h(v, hi, lo);
        ohi[(size_t)orow * E_ + ocol] = hi;
        olo[(size_t)orow * E_ + ocol] = lo;
    }
}

// ================= layernorm -> single fp16 =====================================
__global__ void __launch_bounds__(256) ln_kernel(const float* __restrict__ x,
                                                 const float* __restrict__ w,
                                                 const float* __restrict__ b,
                                                 __half* __restrict__ o)
{
    int row = blockIdx.x;
    int t = threadIdx.x;
    float4 v = ((const float4*)(x + (size_t)row * E_))[t];
    float s  = v.x + v.y + v.z + v.w;
    float sq = v.x*v.x + v.y*v.y + v.z*v.z + v.w*v.w;
    #pragma unroll
    for (int off = 16; off; off >>= 1) {
        s  += __shfl_xor_sync(0xffffffffu, s,  off);
        sq += __shfl_xor_sync(0xffffffffu, sq, off);
    }
    __shared__ float ss[8], ssq[8];
    int warp = t >> 5, lane = t & 31;
    if (lane == 0) { ss[warp] = s; ssq[warp] = sq; }
    __syncthreads();
    float tot = 0.f, totq = 0.f;
    #pragma unroll
    for (int i = 0; i < 8; i++) { tot += ss[i]; totq += ssq[i]; }
    float mu  = tot * (1.0f / E_);
    float var = totq * (1.0f / E_) - mu * mu;
    float rs  = rsqrtf(var + 1e-5f);
    float4 w4 = ((const float4*)w)[t];
    float4 b4 = ((const float4*)b)[t];
    float r0 = (v.x - mu) * rs * w4.x + b4.x;
    float r1 = (v.y - mu) * rs * w4.y + b4.y;
    float r2 = (v.z - mu) * rs * w4.z + b4.z;
    float r3 = (v.w - mu) * rs * w4.w + b4.w;
    uint2 p = { f22u(r0, r1), f22u(r2, r3) };
    ((uint2*)(o + (size_t)row * E_))[t] = p;
}

// ================= mma.sync fp16 2-product GEMM =================================
// C[M,N] = A[M,K] * (Bhi+Blo)[N,K]^T.  A single fp16, B split fp16 hi/lo.
// 128x128 tile, K-chunk 32, 8 warps (2x4), warp tile 64x32, 4-stage cp.async.
// EPI 0: scatter fp16 q/k/v   EPI 1: fp32 out = acc+bias+resid
// EPI 2: fp16 out = relu(acc+bias)
#define ST_A     8192                 // 128 rows x 64B
#define STAGE_B  (3*ST_A)             // A, Bhi, Blo = 24 KB
#define NSTAGE   4
#define SMEM_GEMM (NSTAGE*STAGE_B)    // 96 KB

__device__ __forceinline__ uint32_t swz(int row, int cb) {
    return (uint32_t)((row << 6) + ((cb ^ ((row >> 1) & 3)) << 4));
}

template<int EPI>
__global__ void __launch_bounds__(256) tgemm_kernel(
    const __half* __restrict__ A,
    const __half* __restrict__ Bhi, const __half* __restrict__ Blo,
    int M, int N, int K,
    const float* __restrict__ bias, const float* __restrict__ resid,
    float* __restrict__ outf, __half* __restrict__ outh,
    __half* __restrict__ qo, __half* __restrict__ ko, __half* __restrict__ vo)
{
    extern __shared__ char smem[];
    uint32_t sb = smem_to_u32(smem);
    int tid  = threadIdx.x;
    int lane = tid & 31, wid = tid >> 5;
    int bm = blockIdx.y, bn = blockIdx.x;
    int wm = wid >> 2, wn = wid & 3;

    const char* pA  = (const char*)A;
    const char* pBh = (const char*)Bhi;
    const char* pBl = (const char*)Blo;
    const int K2 = K * 2;
    const size_t aBase = (size_t)(bm * 128) * K2;
    const size_t bBase = (size_t)(bn * 128) * K2;
    const int nch = K >> 5;

    int rr0 = tid >> 2,          cb0 = tid & 3;
    int rr1 = (tid + 256) >> 2;  // same cb

    int a_row = wm * 64 + (lane & 15);
    int a_cbo = lane >> 4;
    int bg = lane >> 3, br = lane & 7;
    int b_row = wn * 32 + ((bg >> 1) << 3) + br;
    int b_cbo = bg & 1;

    float acc[4][4][4];
    #pragma unroll
    for (int a = 0; a < 4; a++)
        #pragma unroll
        for (int nb = 0; nb < 4; nb++)
            #pragma unroll
            for (int i = 0; i < 4; i++) acc[a][nb][i] = 0.f;

    #define LOAD_STAGE(sidx, kb) do {                                   \
        uint32_t s_ = sb + (uint32_t)(sidx) * STAGE_B;                   \
        uint32_t o0 = swz(rr0, cb0), o1 = swz(rr1, cb0);                 \
        size_t ga0 = aBase + (size_t)rr0 * K2 + (kb) + cb0 * 16;         \
        size_t ga1 = aBase + (size_t)rr1 * K2 + (kb) + cb0 * 16;         \
        size_t gb0 = bBase + (size_t)rr0 * K2 + (kb) + cb0 * 16;         \
        size_t gb1 = bBase + (size_t)rr1 * K2 + (kb) + cb0 * 16;         \
        cp16(s_ + o0,          pA  + ga0);                               \
        cp16(s_ + o1,          pA  + ga1);                               \
        cp16(s_ + ST_A + o0,   pBh + gb0);                               \
        cp16(s_ + ST_A + o1,   pBh + gb1);                               \
        cp16(s_ + 2*ST_A + o0, pBl + gb0);                               \
        cp16(s_ + 2*ST_A + o1, pBl + gb1);                               \
    } while (0)

    LOAD_STAGE(0, 0);    CP_COMMIT();
    LOAD_STAGE(1, 64);   CP_COMMIT();
    LOAD_STAGE(2, 128);  CP_COMMIT();

    for (int c = 0; c < nch; c++) {
        CP_WAIT2();
        __syncthreads();
        if (c + 3 < nch) LOAD_STAGE((c + 3) & 3, (size_t)(c + 3) * 64);
        CP_COMMIT();

        uint32_t s = sb + (uint32_t)(c & 3) * STAGE_B;
        #pragma unroll
        for (int ks = 0; ks < 2; ks++) {
            uint32_t af[4][4];
            int acb = ks * 2 + a_cbo;
            #pragma unroll
            for (int a = 0; a < 4; a++)
                ldsm4(af[a], s + swz(a_row + a * 16, acb));
            uint32_t bh[2][4], bl[2][4];
            int bcb = ks * 2 + b_cbo;
            #pragma unroll
            for (int p = 0; p < 2; p++) {
                uint32_t bd = s + ST_A + swz(b_row + p * 16, bcb);
                ldsm4(bh[p], bd);
                ldsm4(bl[p], bd + ST_A);
            }
            #pragma unroll
            for (int a = 0; a < 4; a++)
                #pragma unroll
                for (int p = 0; p < 2; p++)
                    #pragma unroll
                    for (int h = 0; h < 2; h++) {
                        int nb = p * 2 + h;
                        mma16816(acc[a][nb], af[a], bh[p][2*h], bh[p][2*h+1]);
                        mma16816(acc[a][nb], af[a], bl[p][2*h], bl[p][2*h+1]);
                    }
        }
    }
    #undef LOAD_STAGE

    // ---- epilogue ----
    int erow0 = bm * 128 + wm * 64 + (lane >> 2);
    int ecol0 = bn * 128 + wn * 32 + 2 * (lane & 3);

    #pragma unroll
    for (int a = 0; a < 4; a++) {
        #pragma unroll
        for (int nb = 0; nb < 4; nb++) {
            int gn = ecol0 + nb * 8;
            #pragma unroll
            for (int half = 0; half < 2; half++) {
                int gm = erow0 + a * 16 + half * 8;
                float v0 = acc[a][nb][half * 2 + 0];
                float v1 = acc[a][nb][half * 2 + 1];
                if (EPI == 0) {
                    int which = gn >> 10;
                    int w = gn & (E_ - 1);
                    int hh = w >> 6, dd = w & 63;
                    int bk = gm / T_, tt = gm - bk * T_;
                    __half* dst = (which == 0) ? qo : (which == 1) ? ko : vo;
                    uint32_t o = f22u(v0, v1);
                    *(uint32_t*)(dst + (((size_t)(bk * H_ + hh)) * T_ + tt) * HS_ + dd) = o;
                } else if (EPI == 1) {
                    const float2 bv = *(const float2*)(bias + gn);
                    const float2 rv = *(const float2*)(resid + (size_t)gm * N + gn);
                    float2 o = {v0 + bv.x + rv.x, v1 + bv.y + rv.y};
                    *(float2*)(outf + (size_t)gm * N + gn) = o;
                } else {
                    const float2 bv = *(const float2*)(bias + gn);
                    uint32_t o = f22u(fmaxf(v0 + bv.x, 0.f), fmaxf(v1 + bv.y, 0.f));
                    *(uint32_t*)(outh + (size_t)gm * N + gn) = o;
                }
            }
        }
    }
}

// ================= HMMA flash attention =========================================
// fp16 QKV [B,H,T,HS], HS=64. Block: 128 thr (4 warps), 64-query tile.
// Warp w: rows 16w..16w+15. S = Q@K^T (m16n8k16), online softmax in regs,
// P repacked to a-frags, O += P@V. cp.async double-buffered K/V tiles.
#define KVOFF(row, cb) ((uint32_t)(((row) << 7) + ((((cb) ^ ((row) & 7))) << 4)))

__global__ void __launch_bounds__(128) attn_kernel(
    const __half* __restrict__ Qg, const __half* __restrict__ Kg,
    const __half* __restrict__ Vg, __half* __restrict__ Og)
{
    __shared__ __half Qs[4096];
    __shared__ __half Ks[2][4096];
    __shared__ __half Vs[2][4096];

    int qt = blockIdx.x, bh = blockIdx.y;
    int q0 = qt * 64;
    int tid = threadIdx.x, lane = tid & 31, w = tid >> 5;
    const char* qg = (const char*)(Qg + (size_t)bh * T_ * HS_) + (size_t)q0 * 128;
    const char* kg = (const char*)(Kg + (size_t)bh * T_ * HS_);
    const char* vg = (const char*)(Vg + (size_t)bh * T_ * HS_);
    uint32_t sq = smem_to_u32(Qs);
    uint32_t sk0 = smem_to_u32(Ks[0]), sk1 = smem_to_u32(Ks[1]);
    uint32_t sv0 = smem_to_u32(Vs[0]), sv1 = smem_to_u32(Vs[1]);

    // prologue: Q + K/V tile 0
    #pragma unroll
    for (int j = 0; j < 4; j++) {
        int i = tid + j * 128;
        int row = i >> 3, cb = i & 7;
        uint32_t o = KVOFF(row, cb);
        size_t g = (size_t)row * 128 + cb * 16;
        cp16(sq + o, qg + g);
        cp16(sk0 + o, kg + g);
        cp16(sv0 + o, vg + g);
    }
    CP_COMMIT();
    CP_WAIT0();
    __syncthreads();

    // Q a-frags (resident in registers for whole kernel)
    int mid = lane >> 3, r8 = lane & 7;
    uint32_t afr[4][4];
    #pragma unroll
    for (int s = 0; s < 4; s++) {
        int row = 16 * w + ((mid & 1) << 3) + r8;
        int cb = s * 2 + (mid >> 1);
        ldsm4(afr[s], sq + KVOFF(row, cb));
    }

    float o_acc[8][4];
    #pragma unroll
    for (int a = 0; a < 8; a++)
        #pragma unroll
        for (int i = 0; i < 4; i++) o_acc[a][i] = 0.f;
    float mr0 = -1e30f, mr1 = -1e30f, lr0 = 0.f, lr1 = 0.f;

    int nkt = qt + 1;
    int myrow0 = 16 * w + (lane >> 2);          // local row within 64-tile
    int mycol0 = 2 * (lane & 3);

    for (int kt = 0; kt < nkt; kt++) {
        __syncthreads();           // all warps done with buffer (kt+1)&1's old data
        if (kt + 1 < nkt) {
            uint32_t dk = (kt & 1) ? sk0 : sk1;   // buffer (kt+1)&1
            uint32_t dv = (kt & 1) ? sv0 : sv1;
            const char* kg_ = kg + (size_t)(kt + 1) * 64 * 128;
            const char* vg_ = vg + (size_t)(kt + 1) * 64 * 128;
            #pragma unroll
            for (int j = 0; j < 4; j++) {
                int i = tid + j * 128;
                int row = i >> 3, cb = i & 7;
                uint32_t o = KVOFF(row, cb);
                size_t g = (size_t)row * 128 + cb * 16;
                cp16(dk + o, kg_ + g);
                cp16(dv + o, vg_ + g);
            }
        }
        CP_COMMIT();
        CP_WAIT1();                // current tile kt's loads complete (own)
        __syncthreads();           // everyone's loads complete

        uint32_t skb = (kt & 1) ? sk1 : sk0;
        uint32_t svb = (kt & 1) ? sv1 : sv0;

        // ---- S = Q @ K^T ----
        float sA[8][4];
        #pragma unroll
        for (int e = 0; e < 8; e++)
            #pragma unroll
            for (int i = 0; i < 4; i++) sA[e][i] = 0.f;
        #pragma unroll
        for (int s = 0; s < 4; s++) {
            #pragma unroll
            for (int j = 0; j < 4; j++) {
                int row = j * 16 + ((mid >> 1) << 3) + r8;
                int cb = s * 2 + (mid & 1);
                uint32_t bk[4];
                ldsm4(bk, skb + KVOFF(row, cb));
                mma16816(sA[2*j],   afr[s], bk[0], bk[1]);
                mma16816(sA[2*j+1], afr[s], bk[2], bk[3]);
            }
        }

        // ---- scale + causal mask (diagonal tile only) ----
        #pragma unroll
        for (int e = 0; e < 8; e++)
            #pragma unroll
            for (int i = 0; i < 4; i++) sA[e][i] *= 0.03125f;
        if (kt == qt) {
            #pragma unroll
            for (int e = 0; e < 8; e++) {
                int kc = e * 8 + mycol0;
                if (kc     > myrow0)     sA[e][0] = -1e30f;
                if (kc + 1 > myrow0)     sA[e][1] = -1e30f;
                if (kc     > myrow0 + 8) sA[e][2] = -1e30f;
                if (kc + 1 > myrow0 + 8) sA[e][3] = -1e30f;
            }
        }

        // ---- online softmax (rows r0 and r0+8) ----
        float mx0 = -1e30f, mx1 = -1e30f;
        #pragma unroll
        for (int e = 0; e < 8; e++) {
            mx0 = fmaxf(mx0, fmaxf(sA[e][0], sA[e][1]));
            mx1 = fmaxf(mx1, fmaxf(sA[e][2], sA[e][3]));
        }
        mx0 = fmaxf(mx0, __shfl_xor_sync(0xffffffffu, mx0, 1));
        mx0 = fmaxf(mx0, __shfl_xor_sync(0xffffffffu, mx0, 2));
        mx1 = fmaxf(mx1, __shfl_xor_sync(0xffffffffu, mx1, 1));
        mx1 = fmaxf(mx1, __shfl_xor_sync(0xffffffffu, mx1, 2));
        float mn0 = fmaxf(mr0, mx0), mn1 = fmaxf(mr1, mx1);
        float al0 = __expf(mr0 - mn0), al1 = __expf(mr1 - mn1);
        mr0 = mn0; mr1 = mn1;

        float sum0 = 0.f, sum1 = 0.f;
        uint32_t pa[4][4];
        #pragma unroll
        for (int e = 0; e < 8; e++) {
            float p0 = __expf(sA[e][0] - mn0);
            float p1 = __expf(sA[e][1] - mn0);
            float p2 = __expf(sA[e][2] - mn1);
            float p3 = __expf(sA[e][3] - mn1);
            sum0 += p0 + p1; sum1 += p2 + p3;
            int t = e >> 1, od = (e & 1) * 2;
            pa[t][od]     = f22u(p0, p1);
            pa[t][od + 1] = f22u(p2, p3);
        }
        sum0 += __shfl_xor_sync(0xffffffffu, sum0, 1);
        sum0 += __shfl_xor_sync(0xffffffffu, sum0, 2);
        sum1 += __shfl_xor_sync(0xffffffffu, sum1, 1);
        sum1 += __shfl_xor_sync(0xffffffffu, sum1, 2);
        lr0 = lr0 * al0 + sum0;
        lr1 = lr1 * al1 + sum1;

        #pragma unroll
        for (int a = 0; a < 8; a++) {
            o_acc[a][0] *= al0; o_acc[a][1] *= al0;
            o_acc[a][2] *= al1; o_acc[a][3] *= al1;
        }

        // ---- O += P @ V ----
        #pragma unroll
        for (int t = 0; t < 4; t++) {
            #pragma unroll
            for (int j = 0; j < 4; j++) {
                int row = t * 16 + ((mid & 1) << 3) + r8;
                int cb = j * 2 + (mid >> 1);
                uint32_t bv[4];
                ldsm4t(bv, svb + KVOFF(row, cb));
                mma16816(o_acc[2*j],   pa[t], bv[0], bv[1]);
                mma16816(o_acc[2*j+1], pa[t], bv[2], bv[3]);
            }
        }
    }

    float inv0 = 1.0f / lr0, inv1 = 1.0f / lr1;
    int b = bh >> 4, h = bh & 15;
    int gr0 = q0 + myrow0, gr1 = gr0 + 8;
    #pragma unroll
    for (int a = 0; a < 8; a++) {
        int d = a * 8 + mycol0;
        *(uint32_t*)(Og + (((size_t)(b * T_ + gr0)) * H_ + h) * HS_ + d) =
            f22u(o_acc[a][0] * inv0, o_acc[a][1] * inv0);
        *(uint32_t*)(Og + (((size_t)(b * T_ + gr1)) * H_ + h) * HS_ + d) =
            f22u(o_acc[a][2] * inv1, o_acc[a][3] * inv1);
    }
}

// ---------------- launch --------------------------------------------------------
extern "C" void kernel_launch(void* const* d_in, const int* in_sizes, int n_in,
                              void* d_out, int out_size)
{
    const float* x    = (const float*)d_in[0];
    const float* Wq   = (const float*)d_in[1];
    const float* Wk   = (const float*)d_in[2];
    const float* Wv   = (const float*)d_in[3];
    const float* Wo   = (const float*)d_in[4];
    const float* bo   = (const float*)d_in[5];
    const float* W1   = (const float*)d_in[6];
    const float* b1   = (const float*)d_in[7];
    const float* W2   = (const float*)d_in[8];
    const float* b2   = (const float*)d_in[9];
    const float* ln1w = (const float*)d_in[10];
    const float* ln1b = (const float*)d_in[11];
    const float* ln2w = (const float*)d_in[12];
    const float* ln2b = (const float*)d_in[13];
    float* out = (float*)d_out;

    __half *ph, *pat, *pf1, *pq, *pk, *pv;
    __half *wqkvh, *wqkvl, *woh, *wol, *w1h, *w1l, *w2h, *w2l;
    cudaGetSymbolAddress((void**)&ph,    g_h);
    cudaGetSymbolAddress((void**)&pat,   g_at);
    cudaGetSymbolAddress((void**)&pf1,   g_f1);
    cudaGetSymbolAddress((void**)&pq,    g_q);
    cudaGetSymbolAddress((void**)&pk,    g_k);
    cudaGetSymbolAddress((void**)&pv,    g_v);
    cudaGetSymbolAddress((void**)&wqkvh, g_wqkv_hi);
    cudaGetSymbolAddress((void**)&wqkvl, g_wqkv_lo);
    cudaGetSymbolAddress((void**)&woh,   g_wo_hi);
    cudaGetSymbolAddress((void**)&wol,   g_wo_lo);
    cudaGetSymbolAddress((void**)&w1h,   g_w1_hi);
    cudaGetSymbolAddress((void**)&w1l,   g_w1_lo);
    cudaGetSymbolAddress((void**)&w2h,   g_w2_hi);
    cudaGetSymbolAddress((void**)&w2l,   g_w2_lo);

    cudaFuncSetAttribute(tgemm_kernel<0>, cudaFuncAttributeMaxDynamicSharedMemorySize, SMEM_GEMM);
    cudaFuncSetAttribute(tgemm_kernel<1>, cudaFuncAttributeMaxDynamicSharedMemorySize, SMEM_GEMM);
    cudaFuncSetAttribute(tgemm_kernel<2>, cudaFuncAttributeMaxDynamicSharedMemorySize, SMEM_GEMM);

    dim3 tb(32, 8);

    // weight prep (transpose + fp16 split)
    trans_qkv_kernel<<<dim3(2, 32, 48), tb>>>(Wq, Wk, Wv, wqkvh, wqkvl);
    trans_split_kernel<<<dim3(32, 32), tb>>>(Wo, E_, E_, woh, wol);
    trans_split_kernel<<<dim3(128, 32), tb>>>(W1, E_, FF_, w1h, w1l);
    trans_split_kernel<<<dim3(32, 128), tb>>>(W2, FF_, E_, w2h, w2l);

    // h = LN1(x) -> fp16
    ln_kernel<<<M_, 256>>>(x, ln1w, ln1b, ph);

    // q,k,v = h @ Wqkv (scatter fp16 [B,H,T,HS])
    tgemm_kernel<0><<<dim3(3*E_/128, M_/128), 256, SMEM_GEMM>>>(
        ph, wqkvh, wqkvl, M_, 3*E_, E_,
        nullptr, nullptr, nullptr, nullptr, pq, pk, pv);

    // attention (HMMA flash) -> fp16 [B,T,H,HS]
    attn_kernel<<<dim3(T_/64, B_*H_), 128>>>(pq, pk, pv, pat);

    // x1 = x + attn @ Wo + bo  (fp32, into d_out)
    tgemm_kernel<1><<<dim3(E_/128, M_/128), 256, SMEM_GEMM>>>(
        pat, woh, wol, M_, E_, E_,
        bo, x, out, nullptr, nullptr, nullptr, nullptr);

    // h2 = LN2(x1) -> fp16
    ln_kernel<<<M_, 256>>>(out, ln2w, ln2b, ph);

    // f1 = relu(h2 @ W1 + b1) -> fp16
    tgemm_kernel<2><<<dim3(FF_/128, M_/128), 256, SMEM_GEMM>>>(
        ph, w1h, w1l, M_, FF_, E_,
        b1, nullptr, nullptr, pf1, nullptr, nullptr, nullptr);

    // out = x1 + f1 @ W2 + b2
    tgemm_kernel<1><<<dim3(E_/128, M_/128), 256, SMEM_GEMM>>>(
        pf1, w2h, w2l, M_, E_, FF_,
        b2, out, out, nullptr, nullptr, nullptr, nullptr);
}

// round 13
// speedup vs baseline: 7.3797x; 1.3871x over previous
#include <cuda_runtime.h>
#include <cuda_fp16.h>
#include <cstdint>
#include <cstddef>

// Problem constants
#define B_  64
#define T_  320
#define E_  1024
#define H_  16
#define HS_ 64
#define M_  (B_*T_)      // 20480 tokens
#define FF_ (4*E_)       // 4096

// ===================== baseline-PTX helpers (no 'a'-arch features) =============
__device__ __forceinline__ uint32_t smem_to_u32(const void* p) {
    uint32_t a;
    asm("{ .reg .u64 t; cvta.to.shared.u64 t, %1; cvt.u32.u64 %0, t; }" : "=r"(a) : "l"(p));
    return a;
}
__device__ __forceinline__ void cp16(uint32_t s, const void* g) {
    asm volatile("cp.async.cg.shared.global [%0], [%1], 16;" :: "r"(s), "l"(g));
}
#define CP_COMMIT() asm volatile("cp.async.commit_group;" ::: "memory")
#define CP_WAIT0()  asm volatile("cp.async.wait_group 0;"  ::: "memory")
#define CP_WAIT1()  asm volatile("cp.async.wait_group 1;"  ::: "memory")
#define CP_WAIT2()  asm volatile("cp.async.wait_group 2;"  ::: "memory")

__device__ __forceinline__ void ldsm4(uint32_t* r, uint32_t addr) {
    asm volatile("ldmatrix.sync.aligned.m8n8.x4.shared.b16 {%0,%1,%2,%3}, [%4];"
        : "=r"(r[0]), "=r"(r[1]), "=r"(r[2]), "=r"(r[3]) : "r"(addr));
}
__device__ __forceinline__ void ldsm4t(uint32_t* r, uint32_t addr) {
    asm volatile("ldmatrix.sync.aligned.m8n8.x4.trans.shared.b16 {%0,%1,%2,%3}, [%4];"
        : "=r"(r[0]), "=r"(r[1]), "=r"(r[2]), "=r"(r[3]) : "r"(addr));
}
// fp16 MMA, fp32 accumulate
__device__ __forceinline__ void mma16816(float* c, const uint32_t* a,
                                         uint32_t b0, uint32_t b1) {
    asm volatile(
        "mma.sync.aligned.m16n8k16.row.col.f32.f16.f16.f32 "
        "{%0,%1,%2,%3},{%4,%5,%6,%7},{%8,%9},{%0,%1,%2,%3};"
        : "+f"(c[0]), "+f"(c[1]), "+f"(c[2]), "+f"(c[3])
        : "r"(a[0]), "r"(a[1]), "r"(a[2]), "r"(a[3]), "r"(b0), "r"(b1));
}
__device__ __forceinline__ uint32_t f22u(float a, float b) {
    __half2 h = __float22half2_rn(make_float2(a, b));
    return *(uint32_t*)&h;
}

// ===================== device scratch (no allocations allowed) ==================
__device__ __half g_h   [(size_t)M_*E_];     // LN output fp16
__device__ __half g_at  [(size_t)M_*E_];     // attention out [B,T,H,HS]
__device__ __half g_f1  [(size_t)M_*FF_];    // relu(h2@W1+b1)
__device__ __half g_q   [(size_t)M_*E_];     // [B,H,T,HS] fp16
__device__ __half g_k   [(size_t)M_*E_];
__device__ __half g_v   [(size_t)M_*E_];
__device__ __half g_wqkv[(size_t)3*E_*E_];   // [N=3E, K=E] fp16
__device__ __half g_wo  [(size_t)E_*E_];     // [N=E, K=E]
__device__ __half g_w1  [(size_t)FF_*E_];    // [N=4E, K=E]
__device__ __half g_w2  [(size_t)E_*FF_];    // [N=E, K=4E]

// ============ weight prep: transpose fp32 [K,N] -> fp16 [N,K] ===================
__global__ void trans_kernel(const float* __restrict__ in, int K, int N,
                             __half* __restrict__ o)
{
    __shared__ float t[32][33];
    int nb = blockIdx.x * 32, kb = blockIdx.y * 32;
    int tx = threadIdx.x, ty = threadIdx.y;          // 32 x 8
    #pragma unroll
    for (int j = 0; j < 4; j++)
        t[ty + j*8][tx] = in[(size_t)(kb + ty + j*8) * N + nb + tx];
    __syncthreads();
    #pragma unroll
    for (int j = 0; j < 4; j++) {
        float v = t[tx][ty + j*8];
        int orow = nb + ty + j*8, ocol = kb + tx;
        o[(size_t)orow * K + ocol] = __float2half_rn(v);
    }
}

// Wq/Wk/Wv (H,E,HS) -> [3E rows, E cols] transposed fp16
__global__ void trans_qkv_kernel(const float* __restrict__ Wq,
                                 const float* __restrict__ Wk,
                                 const float* __restrict__ Wv,
                                 __half* __restrict__ o)
{
    __shared__ float t[32][33];
    int z = blockIdx.z;
    const float* W = (z < 16) ? Wq : (z < 32) ? Wk : Wv;
    const float* in = W + (size_t)(z & 15) * E_ * HS_;
    int nb = blockIdx.x * 32, kb = blockIdx.y * 32;
    int tx = threadIdx.x, ty = threadIdx.y;
    #pragma unroll
    for (int j = 0; j < 4; j++)
        t[ty + j*8][tx] = in[(size_t)(kb + ty + j*8) * HS_ + nb + tx];
    __syncthreads();
    #pragma unroll
    for (int j = 0; j < 4; j++) {
        float v = t[tx][ty + j*8];
        int orow = z * 64 + nb + ty + j*8;
        int ocol = kb + tx;
        o[(size_t)orow * E_ + ocol] = __float2half_rn(v);
    }
}

// ================= layernorm -> fp16 ============================================
__global__ void __launch_bounds__(256) ln_kernel(const float* __restrict__ x,
                                                 const float* __restrict__ w,
                                                 const float* __restrict__ b,
                                                 __half* __restrict__ o)
{
    int row = blockIdx.x;
    int t = threadIdx.x;
    float4 v = ((const float4*)(x + (size_t)row * E_))[t];
    float s  = v.x + v.y + v.z + v.w;
    float sq = v.x*v.x + v.y*v.y + v.z*v.z + v.w*v.w;
    #pragma unroll
    for (int off = 16; off; off >>= 1) {
        s  += __shfl_xor_sync(0xffffffffu, s,  off);
        sq += __shfl_xor_sync(0xffffffffu, sq, off);
    }
    __shared__ float ss[8], ssq[8];
    int warp = t >> 5, lane = t & 31;
    if (lane == 0) { ss[warp] = s; ssq[warp] = sq; }
    __syncthreads();
    float tot = 0.f, totq = 0.f;
    #pragma unroll
    for (int i = 0; i < 8; i++) { tot += ss[i]; totq += ssq[i]; }
    float mu  = tot * (1.0f / E_);
    float var = totq * (1.0f / E_) - mu * mu;
    float rs  = rsqrtf(var + 1e-5f);
    float4 w4 = ((const float4*)w)[t];
    float4 b4 = ((const float4*)b)[t];
    float r0 = (v.x - mu) * rs * w4.x + b4.x;
    float r1 = (v.y - mu) * rs * w4.y + b4.y;
    float r2 = (v.z - mu) * rs * w4.z + b4.z;
    float r3 = (v.w - mu) * rs * w4.w + b4.w;
    uint2 p = { f22u(r0, r1), f22u(r2, r3) };
    ((uint2*)(o + (size_t)row * E_))[t] = p;
}

// ================= mma.sync fp16 GEMM (single product) ==========================
// C[M,N] = A[M,K] * B[N,K]^T.  128x256 block tile, 8 warps (2x4),
// warp tile 64x64, K-chunk 32, 4-stage cp.async pipeline.
// EPI 0: scatter fp16 q/k/v   EPI 1: fp32 out = acc+bias+resid
// EPI 2: fp16 out = relu(acc+bias)
#define ST_A     8192                 // A: 128 rows x 64B
#define ST_B     16384                // B: 256 rows x 64B
#define STAGE_B  (ST_A+ST_B)          // 24 KB
#define NSTAGE   4
#define SMEM_GEMM (NSTAGE*STAGE_B)    // 96 KB

__device__ __forceinline__ uint32_t swz(int row, int cb) {
    return (uint32_t)((row << 6) + ((cb ^ ((row >> 1) & 3)) << 4));
}

template<int EPI>
__global__ void __launch_bounds__(256) tgemm_kernel(
    const __half* __restrict__ A, const __half* __restrict__ Bw,
    int M, int N, int K,
    const float* __restrict__ bias, const float* __restrict__ resid,
    float* __restrict__ outf, __half* __restrict__ outh,
    __half* __restrict__ qo, __half* __restrict__ ko, __half* __restrict__ vo)
{
    extern __shared__ char smem[];
    uint32_t sb = smem_to_u32(smem);
    int tid  = threadIdx.x;
    int lane = tid & 31, wid = tid >> 5;
    int bm = blockIdx.y, bn = blockIdx.x;
    int wm = wid >> 2, wn = wid & 3;

    const char* pA = (const char*)A;
    const char* pB = (const char*)Bw;
    const int K2 = K * 2;
    const size_t aBase = (size_t)(bm * 128) * K2;
    const size_t bBase = (size_t)(bn * 256) * K2;
    const int nch = K >> 5;

    int cb0 = tid & 3;
    int rA0 = tid >> 2, rA1 = (tid + 256) >> 2;

    int a_row = wm * 64 + (lane & 15);
    int a_cbo = lane >> 4;
    int bg = lane >> 3, br = lane & 7;
    int b_row = wn * 64 + ((bg >> 1) << 3) + br;
    int b_cbo = bg & 1;

    float acc[4][8][4];
    #pragma unroll
    for (int a = 0; a < 4; a++)
        #pragma unroll
        for (int nb = 0; nb < 8; nb++)
            #pragma unroll
            for (int i = 0; i < 4; i++) acc[a][nb][i] = 0.f;

    #define LOAD_STAGE(sidx, kb) do {                                     \
        uint32_t s_ = sb + (uint32_t)(sidx) * STAGE_B;                     \
        cp16(s_ + swz(rA0, cb0), pA + aBase + (size_t)rA0 * K2 + (kb) + cb0 * 16); \
        cp16(s_ + swz(rA1, cb0), pA + aBase + (size_t)rA1 * K2 + (kb) + cb0 * 16); \
        _Pragma("unroll")                                                  \
        for (int j = 0; j < 4; j++) {                                      \
            int rB = (tid + j * 256) >> 2;                                 \
            cp16(s_ + ST_A + swz(rB, cb0),                                 \
                 pB + bBase + (size_t)rB * K2 + (kb) + cb0 * 16);          \
        }                                                                  \
    } while (0)

    LOAD_STAGE(0, 0);    CP_COMMIT();
    LOAD_STAGE(1, 64);   CP_COMMIT();
    LOAD_STAGE(2, 128);  CP_COMMIT();

    for (int c = 0; c < nch; c++) {
        CP_WAIT2();
        __syncthreads();
        if (c + 3 < nch) LOAD_STAGE((c + 3) & 3, (size_t)(c + 3) * 64);
        CP_COMMIT();

        uint32_t s = sb + (uint32_t)(c & 3) * STAGE_B;
        #pragma unroll
        for (int ks = 0; ks < 2; ks++) {
            uint32_t af[4][4];
            int acb = ks * 2 + a_cbo;
            #pragma unroll
            for (int a = 0; a < 4; a++)
                ldsm4(af[a], s + swz(a_row + a * 16, acb));
            int bcb = ks * 2 + b_cbo;
            #pragma unroll
            for (int p = 0; p < 4; p++) {
                uint32_t bf[4];
                ldsm4(bf, s + ST_A + swz(b_row + p * 16, bcb));
                #pragma unroll
                for (int h = 0; h < 2; h++) {
                    int nb = p * 2 + h;
                    #pragma unroll
                    for (int a = 0; a < 4; a++)
                        mma16816(acc[a][nb], af[a], bf[2*h], bf[2*h+1]);
                }
            }
        }
    }
    #undef LOAD_STAGE

    // ---- epilogue ----
    int erow0 = bm * 128 + wm * 64 + (lane >> 2);
    int ecol0 = bn * 256 + wn * 64 + 2 * (lane & 3);

    #pragma unroll
    for (int a = 0; a < 4; a++) {
        #pragma unroll
        for (int nb = 0; nb < 8; nb++) {
            int gn = ecol0 + nb * 8;
            #pragma unroll
            for (int half = 0; half < 2; half++) {
                int gm = erow0 + a * 16 + half * 8;
                float v0 = acc[a][nb][half * 2 + 0];
                float v1 = acc[a][nb][half * 2 + 1];
                if (EPI == 0) {
                    int which = gn >> 10;
                    int w = gn & (E_ - 1);
                    int hh = w >> 6, dd = w & 63;
                    int bk = gm / T_, tt = gm - bk * T_;
                    __half* dst = (which == 0) ? qo : (which == 1) ? ko : vo;
                    uint32_t o = f22u(v0, v1);
                    *(uint32_t*)(dst + (((size_t)(bk * H_ + hh)) * T_ + tt) * HS_ + dd) = o;
                } else if (EPI == 1) {
                    const float2 bv = *(const float2*)(bias + gn);
                    const float2 rv = *(const float2*)(resid + (size_t)gm * N + gn);
                    float2 o = {v0 + bv.x + rv.x, v1 + bv.y + rv.y};
                    *(float2*)(outf + (size_t)gm * N + gn) = o;
                } else {
                    const float2 bv = *(const float2*)(bias + gn);
                    uint32_t o = f22u(fmaxf(v0 + bv.x, 0.f), fmaxf(v1 + bv.y, 0.f));
                    *(uint32_t*)(outh + (size_t)gm * N + gn) = o;
                }
            }
        }
    }
}

// ================= HMMA flash attention =========================================
// fp16 QKV [B,H,T,HS], HS=64. Block: 128 thr (4 warps), 64-query tile.
#define KVOFF(row, cb) ((uint32_t)(((row) << 7) + ((((cb) ^ ((row) & 7))) << 4)))

__global__ void __launch_bounds__(128) attn_kernel(
    const __half* __restrict__ Qg, const __half* __restrict__ Kg,
    const __half* __restrict__ Vg, __half* __restrict__ Og)
{
    __shared__ __half Qs[4096];
    __shared__ __half Ks[2][4096];
    __shared__ __half Vs[2][4096];

    int qt = blockIdx.x, bh = blockIdx.y;
    int q0 = qt * 64;
    int tid = threadIdx.x, lane = tid & 31, w = tid >> 5;
    const char* qg = (const char*)(Qg + (size_t)bh * T_ * HS_) + (size_t)q0 * 128;
    const char* kg = (const char*)(Kg + (size_t)bh * T_ * HS_);
    const char* vg = (const char*)(Vg + (size_t)bh * T_ * HS_);
    uint32_t sq = smem_to_u32(Qs);
    uint32_t sk0 = smem_to_u32(Ks[0]), sk1 = smem_to_u32(Ks[1]);
    uint32_t sv0 = smem_to_u32(Vs[0]), sv1 = smem_to_u32(Vs[1]);

    #pragma unroll
    for (int j = 0; j < 4; j++) {
        int i = tid + j * 128;
        int row = i >> 3, cb = i & 7;
        uint32_t o = KVOFF(row, cb);
        size_t g = (size_t)row * 128 + cb * 16;
        cp16(sq + o, qg + g);
        cp16(sk0 + o, kg + g);
        cp16(sv0 + o, vg + g);
    }
    CP_COMMIT();
    CP_WAIT0();
    __syncthreads();

    int mid = lane >> 3, r8 = lane & 7;
    uint32_t afr[4][4];
    #pragma unroll
    for (int s = 0; s < 4; s++) {
        int row = 16 * w + ((mid & 1) << 3) + r8;
        int cb = s * 2 + (mid >> 1);
        ldsm4(afr[s], sq + KVOFF(row, cb));
    }

    float o_acc[8][4];
    #pragma unroll
    for (int a = 0; a < 8; a++)
        #pragma unroll
        for (int i = 0; i < 4; i++) o_acc[a][i] = 0.f;
    float mr0 = -1e30f, mr1 = -1e30f, lr0 = 0.f, lr1 = 0.f;

    int nkt = qt + 1;
    int myrow0 = 16 * w + (lane >> 2);
    int mycol0 = 2 * (lane & 3);

    for (int kt = 0; kt < nkt; kt++) {
        __syncthreads();
        if (kt + 1 < nkt) {
            uint32_t dk = (kt & 1) ? sk0 : sk1;
            uint32_t dv = (kt & 1) ? sv0 : sv1;
            const char* kg_ = kg + (size_t)(kt + 1) * 64 * 128;
            const char* vg_ = vg + (size_t)(kt + 1) * 64 * 128;
            #pragma unroll
            for (int j = 0; j < 4; j++) {
                int i = tid + j * 128;
                int row = i >> 3, cb = i & 7;
                uint32_t o = KVOFF(row, cb);
                size_t g = (size_t)row * 128 + cb * 16;
                cp16(dk + o, kg_ + g);
                cp16(dv + o, vg_ + g);
            }
        }
        CP_COMMIT();
        CP_WAIT1();
        __syncthreads();

        uint32_t skb = (kt & 1) ? sk1 : sk0;
        uint32_t svb = (kt & 1) ? sv1 : sv0;

        float sA[8][4];
        #pragma unroll
        for (int e = 0; e < 8; e++)
            #pragma unroll
            for (int i = 0; i < 4; i++) sA[e][i] = 0.f;
        #pragma unroll
        for (int s = 0; s < 4; s++) {
            #pragma unroll
            for (int j = 0; j < 4; j++) {
                int row = j * 16 + ((mid >> 1) << 3) + r8;
                int cb = s * 2 + (mid & 1);
                uint32_t bk[4];
                ldsm4(bk, skb + KVOFF(row, cb));
                mma16816(sA[2*j],   afr[s], bk[0], bk[1]);
                mma16816(sA[2*j+1], afr[s], bk[2], bk[3]);
            }
        }

        #pragma unroll
        for (int e = 0; e < 8; e++)
            #pragma unroll
            for (int i = 0; i < 4; i++) sA[e][i] *= 0.03125f;
        if (kt == qt) {
            #pragma unroll
            for (int e = 0; e < 8; e++) {
                int kc = e * 8 + mycol0;
                if (kc     > myrow0)     sA[e][0] = -1e30f;
                if (kc + 1 > myrow0)     sA[e][1] = -1e30f;
                if (kc     > myrow0 + 8) sA[e][2] = -1e30f;
                if (kc + 1 > myrow0 + 8) sA[e][3] = -1e30f;
            }
        }

        float mx0 = -1e30f, mx1 = -1e30f;
        #pragma unroll
        for (int e = 0; e < 8; e++) {
            mx0 = fmaxf(mx0, fmaxf(sA[e][0], sA[e][1]));
            mx1 = fmaxf(mx1, fmaxf(sA[e][2], sA[e][3]));
        }
        mx0 = fmaxf(mx0, __shfl_xor_sync(0xffffffffu, mx0, 1));
        mx0 = fmaxf(mx0, __shfl_xor_sync(0xffffffffu, mx0, 2));
        mx1 = fmaxf(mx1, __shfl_xor_sync(0xffffffffu, mx1, 1));
        mx1 = fmaxf(mx1, __shfl_xor_sync(0xffffffffu, mx1, 2));
        float mn0 = fmaxf(mr0, mx0), mn1 = fmaxf(mr1, mx1);
        float al0 = __expf(mr0 - mn0), al1 = __expf(mr1 - mn1);
        mr0 = mn0; mr1 = mn1;

        float sum0 = 0.f, sum1 = 0.f;
        uint32_t pa[4][4];
        #pragma unroll
        for (int e = 0; e < 8; e++) {
            float p0 = __expf(sA[e][0] - mn0);
            float p1 = __expf(sA[e][1] - mn0);
            float p2 = __expf(sA[e][2] - mn1);
            float p3 = __expf(sA[e][3] - mn1);
            sum0 += p0 + p1; sum1 += p2 + p3;
            int t = e >> 1, od = (e & 1) * 2;
            pa[t][od]     = f22u(p0, p1);
            pa[t][od + 1] = f22u(p2, p3);
        }
        sum0 += __shfl_xor_sync(0xffffffffu, sum0, 1);
        sum0 += __shfl_xor_sync(0xffffffffu, sum0, 2);
        sum1 += __shfl_xor_sync(0xffffffffu, sum1, 1);
        sum1 += __shfl_xor_sync(0xffffffffu, sum1, 2);
        lr0 = lr0 * al0 + sum0;
        lr1 = lr1 * al1 + sum1;

        #pragma unroll
        for (int a = 0; a < 8; a++) {
            o_acc[a][0] *= al0; o_acc[a][1] *= al0;
            o_acc[a][2] *= al1; o_acc[a][3] *= al1;
        }

        #pragma unroll
        for (int t = 0; t < 4; t++) {
            #pragma unroll
            for (int j = 0; j < 4; j++) {
                int row = t * 16 + ((mid & 1) << 3) + r8;
                int cb = j * 2 + (mid >> 1);
                uint32_t bv[4];
                ldsm4t(bv, svb + KVOFF(row, cb));
                mma16816(o_acc[2*j],   pa[t], bv[0], bv[1]);
                mma16816(o_acc[2*j+1], pa[t], bv[2], bv[3]);
            }
        }
    }

    float inv0 = 1.0f / lr0, inv1 = 1.0f / lr1;
    int b = bh >> 4, h = bh & 15;
    int gr0 = q0 + myrow0, gr1 = gr0 + 8;
    #pragma unroll
    for (int a = 0; a < 8; a++) {
        int d = a * 8 + mycol0;
        *(uint32_t*)(Og + (((size_t)(b * T_ + gr0)) * H_ + h) * HS_ + d) =
            f22u(o_acc[a][0] * inv0, o_acc[a][1] * inv0);
        *(uint32_t*)(Og + (((size_t)(b * T_ + gr1)) * H_ + h) * HS_ + d) =
            f22u(o_acc[a][2] * inv1, o_acc[a][3] * inv1);
    }
}

// ---------------- launch --------------------------------------------------------
extern "C" void kernel_launch(void* const* d_in, const int* in_sizes, int n_in,
                              void* d_out, int out_size)
{
    const float* x    = (const float*)d_in[0];
    const float* Wq   = (const float*)d_in[1];
    const float* Wk   = (const float*)d_in[2];
    const float* Wv   = (const float*)d_in[3];
    const float* Wo   = (const float*)d_in[4];
    const float* bo   = (const float*)d_in[5];
    const float* W1   = (const float*)d_in[6];
    const float* b1   = (const float*)d_in[7];
    const float* W2   = (const float*)d_in[8];
    const float* b2   = (const float*)d_in[9];
    const float* ln1w = (const float*)d_in[10];
    const float* ln1b = (const float*)d_in[11];
    const float* ln2w = (const float*)d_in[12];
    const float* ln2b = (const float*)d_in[13];
    float* out = (float*)d_out;

    __half *ph, *pat, *pf1, *pq, *pk, *pv, *wqkv, *wo, *w1, *w2;
    cudaGetSymbolAddress((void**)&ph,   g_h);
    cudaGetSymbolAddress((void**)&pat,  g_at);
    cudaGetSymbolAddress((void**)&pf1,  g_f1);
    cudaGetSymbolAddress((void**)&pq,   g_q);
    cudaGetSymbolAddress((void**)&pk,   g_k);
    cudaGetSymbolAddress((void**)&pv,   g_v);
    cudaGetSymbolAddress((void**)&wqkv, g_wqkv);
    cudaGetSymbolAddress((void**)&wo,   g_wo);
    cudaGetSymbolAddress((void**)&w1,   g_w1);
    cudaGetSymbolAddress((void**)&w2,   g_w2);

    cudaFuncSetAttribute(tgemm_kernel<0>, cudaFuncAttributeMaxDynamicSharedMemorySize, SMEM_GEMM);
    cudaFuncSetAttribute(tgemm_kernel<1>, cudaFuncAttributeMaxDynamicSharedMemorySize, SMEM_GEMM);
    cudaFuncSetAttribute(tgemm_kernel<2>, cudaFuncAttributeMaxDynamicSharedMemorySize, SMEM_GEMM);

    dim3 tb(32, 8);

    // weight prep (transpose to fp16 [N,K])
    trans_qkv_kernel<<<dim3(2, 32, 48), tb>>>(Wq, Wk, Wv, wqkv);
    trans_kernel<<<dim3(32, 32), tb>>>(Wo, E_, E_, wo);
    trans_kernel<<<dim3(128, 32), tb>>>(W1, E_, FF_, w1);
    trans_kernel<<<dim3(32, 128), tb>>>(W2, FF_, E_, w2);

    // h = LN1(x) -> fp16
    ln_kernel<<<M_, 256>>>(x, ln1w, ln1b, ph);

    // q,k,v = h @ Wqkv (scatter fp16 [B,H,T,HS])
    tgemm_kernel<0><<<dim3(3*E_/256, M_/128), 256, SMEM_GEMM>>>(
        ph, wqkv, M_, 3*E_, E_,
        nullptr, nullptr, nullptr, nullptr, pq, pk, pv);

    // attention (HMMA flash) -> fp16 [B,T,H,HS]
    attn_kernel<<<dim3(T_/64, B_*H_), 128>>>(pq, pk, pv, pat);

    // x1 = x + attn @ Wo + bo  (fp32, into d_out)
    tgemm_kernel<1><<<dim3(E_/256, M_/128), 256, SMEM_GEMM>>>(
        pat, wo, M_, E_, E_,
        bo, x, out, nullptr, nullptr, nullptr, nullptr);

    // h2 = LN2(x1) -> fp16
    ln_kernel<<<M_, 256>>>(out, ln2w, ln2b, ph);

    // f1 = relu(h2 @ W1 + b1) -> fp16
    tgemm_kernel<2><<<dim3(FF_/256, M_/128), 256, SMEM_GEMM>>>(
        ph, w1, M_, FF_, E_,
        b1, nullptr, nullptr, pf1, nullptr, nullptr, nullptr);

    // out = x1 + f1 @ W2 + b2
    tgemm_kernel<1><<<dim3(E_/256, M_/128), 256, SMEM_GEMM>>>(
        pf1, w2, M_, E_, FF_,
        b2, out, out, nullptr, nullptr, nullptr, nullptr);
}

// round 14
// speedup vs baseline: 8.7236x; 1.1821x over previous
#include <cuda_runtime.h>
#include <cuda_fp16.h>
#include <cstdint>
#include <cstddef>

// Problem constants
#define B_  64
#define T_  320
#define E_  1024
#define H_  16
#define HS_ 64
#define M_  (B_*T_)      // 20480 tokens
#define FF_ (4*E_)       // 4096

// ===================== baseline-PTX helpers (no 'a'-arch features) =============
__device__ __forceinline__ uint32_t smem_to_u32(const void* p) {
    uint32_t a;
    asm("{ .reg .u64 t; cvta.to.shared.u64 t, %1; cvt.u32.u64 %0, t; }" : "=r"(a) : "l"(p));
    return a;
}
__device__ __forceinline__ void cp16(uint32_t s, const void* g) {
    asm volatile("cp.async.cg.shared.global [%0], [%1], 16;" :: "r"(s), "l"(g));
}
#define CP_COMMIT() asm volatile("cp.async.commit_group;" ::: "memory")
#define CP_WAIT0()  asm volatile("cp.async.wait_group 0;"  ::: "memory")
#define CP_WAIT1()  asm volatile("cp.async.wait_group 1;"  ::: "memory")

__device__ __forceinline__ void ldsm4(uint32_t* r, uint32_t addr) {
    asm volatile("ldmatrix.sync.aligned.m8n8.x4.shared.b16 {%0,%1,%2,%3}, [%4];"
        : "=r"(r[0]), "=r"(r[1]), "=r"(r[2]), "=r"(r[3]) : "r"(addr));
}
__device__ __forceinline__ void ldsm4t(uint32_t* r, uint32_t addr) {
    asm volatile("ldmatrix.sync.aligned.m8n8.x4.trans.shared.b16 {%0,%1,%2,%3}, [%4];"
        : "=r"(r[0]), "=r"(r[1]), "=r"(r[2]), "=r"(r[3]) : "r"(addr));
}
// fp16 MMA, fp32 accumulate
__device__ __forceinline__ void mma16816(float* c, const uint32_t* a,
                                         uint32_t b0, uint32_t b1) {
    asm volatile(
        "mma.sync.aligned.m16n8k16.row.col.f32.f16.f16.f32 "
        "{%0,%1,%2,%3},{%4,%5,%6,%7},{%8,%9},{%0,%1,%2,%3};"
        : "+f"(c[0]), "+f"(c[1]), "+f"(c[2]), "+f"(c[3])
        : "r"(a[0]), "r"(a[1]), "r"(a[2]), "r"(a[3]), "r"(b0), "r"(b1));
}
__device__ __forceinline__ uint32_t f22u(float a, float b) {
    __half2 h = __float22half2_rn(make_float2(a, b));
    return *(uint32_t*)&h;
}

// 128B-row XOR swizzle: conflict-free for cp.async fill and ldmatrix reads
#define SWZ128(row, cb) ((uint32_t)(((row) << 7) + ((((cb) ^ ((row) & 7))) << 4)))

// ===================== device scratch (no allocations allowed) ==================
__device__ __half g_h   [(size_t)M_*E_];     // LN output fp16
__device__ __half g_at  [(size_t)M_*E_];     // attention out [B,T,H,HS]
__device__ __half g_f1  [(size_t)M_*FF_];    // relu(h2@W1+b1)
__device__ __half g_q   [(size_t)M_*E_];     // [B,H,T,HS] fp16
__device__ __half g_k   [(size_t)M_*E_];
__device__ __half g_v   [(size_t)M_*E_];
__device__ __half g_wqkv[(size_t)3*E_*E_];   // [N=3E, K=E] fp16
__device__ __half g_wo  [(size_t)E_*E_];     // [N=E, K=E]
__device__ __half g_w1  [(size_t)FF_*E_];    // [N=4E, K=E]
__device__ __half g_w2  [(size_t)E_*FF_];    // [N=E, K=4E]

// ============ weight prep: transpose fp32 [K,N] -> fp16 [N,K] ===================
__global__ void trans_kernel(const float* __restrict__ in, int K, int N,
                             __half* __restrict__ o)
{
    __shared__ float t[32][33];
    int nb = blockIdx.x * 32, kb = blockIdx.y * 32;
    int tx = threadIdx.x, ty = threadIdx.y;          // 32 x 8
    #pragma unroll
    for (int j = 0; j < 4; j++)
        t[ty + j*8][tx] = in[(size_t)(kb + ty + j*8) * N + nb + tx];
    __syncthreads();
    #pragma unroll
    for (int j = 0; j < 4; j++) {
        float v = t[tx][ty + j*8];
        int orow = nb + ty + j*8, ocol = kb + tx;
        o[(size_t)orow * K + ocol] = __float2half_rn(v);
    }
}

// Wq/Wk/Wv (H,E,HS) -> [3E rows, E cols] transposed fp16
__global__ void trans_qkv_kernel(const float* __restrict__ Wq,
                                 const float* __restrict__ Wk,
                                 const float* __restrict__ Wv,
                                 __half* __restrict__ o)
{
    __shared__ float t[32][33];
    int z = blockIdx.z;
    const float* W = (z < 16) ? Wq : (z < 32) ? Wk : Wv;
    const float* in = W + (size_t)(z & 15) * E_ * HS_;
    int nb = blockIdx.x * 32, kb = blockIdx.y * 32;
    int tx = threadIdx.x, ty = threadIdx.y;
    #pragma unroll
    for (int j = 0; j < 4; j++)
        t[ty + j*8][tx] = in[(size_t)(kb + ty + j*8) * HS_ + nb + tx];
    __syncthreads();
    #pragma unroll
    for (int j = 0; j < 4; j++) {
        float v = t[tx][ty + j*8];
        int orow = z * 64 + nb + ty + j*8;
        int ocol = kb + tx;
        o[(size_t)orow * E_ + ocol] = __float2half_rn(v);
    }
}

// ================= layernorm -> fp16 ============================================
__global__ void __launch_bounds__(256) ln_kernel(const float* __restrict__ x,
                                                 const float* __restrict__ w,
                                                 const float* __restrict__ b,
                                                 __half* __restrict__ o)
{
    int row = blockIdx.x;
    int t = threadIdx.x;
    float4 v = ((const float4*)(x + (size_t)row * E_))[t];
    float s  = v.x + v.y + v.z + v.w;
    float sq = v.x*v.x + v.y*v.y + v.z*v.z + v.w*v.w;
    #pragma unroll
    for (int off = 16; off; off >>= 1) {
        s  += __shfl_xor_sync(0xffffffffu, s,  off);
        sq += __shfl_xor_sync(0xffffffffu, sq, off);
    }
    __shared__ float ss[8], ssq[8];
    int warp = t >> 5, lane = t & 31;
    if (lane == 0) { ss[warp] = s; ssq[warp] = sq; }
    __syncthreads();
    float tot = 0.f, totq = 0.f;
    #pragma unroll
    for (int i = 0; i < 8; i++) { tot += ss[i]; totq += ssq[i]; }
    float mu  = tot * (1.0f / E_);
    float var = totq * (1.0f / E_) - mu * mu;
    float rs  = rsqrtf(var + 1e-5f);
    float4 w4 = ((const float4*)w)[t];
    float4 b4 = ((const float4*)b)[t];
    float r0 = (v.x - mu) * rs * w4.x + b4.x;
    float r1 = (v.y - mu) * rs * w4.y + b4.y;
    float r2 = (v.z - mu) * rs * w4.z + b4.z;
    float r3 = (v.w - mu) * rs * w4.w + b4.w;
    uint2 p = { f22u(r0, r1), f22u(r2, r3) };
    ((uint2*)(o + (size_t)row * E_))[t] = p;
}

// ================= mma.sync fp16 GEMM ===========================================
// C[M,N] = A[M,K] * B[N,K]^T. 128x256 block tile, 8 warps (2x4), warp tile 64x64,
// K-chunk 64, 2-stage cp.async pipeline (one barrier per chunk).
// EPI 0: scatter fp16 q/k/v   EPI 1: fp32 out = acc+bias+resid
// EPI 2: fp16 out = relu(acc+bias)
#define ST_A     16384                 // A: 128 rows x 128B
#define ST_B     32768                 // B: 256 rows x 128B
#define STAGE_SZ (ST_A+ST_B)           // 48 KB
#define SMEM_GEMM (2*STAGE_SZ)         // 96 KB

template<int EPI>
__global__ void __launch_bounds__(256, 1) tgemm_kernel(
    const __half* __restrict__ A, const __half* __restrict__ Bw,
    int M, int N, int K,
    const float* __restrict__ bias, const float* __restrict__ resid,
    float* __restrict__ outf, __half* __restrict__ outh,
    __half* __restrict__ qo, __half* __restrict__ ko, __half* __restrict__ vo)
{
    extern __shared__ char smem[];
    uint32_t sb = smem_to_u32(smem);
    int tid  = threadIdx.x;
    int lane = tid & 31, wid = tid >> 5;
    int bm = blockIdx.y, bn = blockIdx.x;
    int wm = wid >> 2, wn = wid & 3;

    const char* pA = (const char*)A;
    const char* pB = (const char*)Bw;
    const int K2 = K * 2;                    // bytes per row
    const size_t aBase = (size_t)(bm * 128) * K2;
    const size_t bBase = (size_t)(bn * 256) * K2;
    const int nch = K >> 6;                  // 64-K chunks

    int a_row = wm * 64 + (lane & 15);
    int a_cbo = lane >> 4;                   // 0/1
    int bg = lane >> 3, br = lane & 7;
    int b_row = wn * 64 + ((bg >> 1) << 3) + br;
    int b_cbo = bg & 1;

    float acc[4][8][4];
    #pragma unroll
    for (int a = 0; a < 4; a++)
        #pragma unroll
        for (int nb = 0; nb < 8; nb++)
            #pragma unroll
            for (int i = 0; i < 4; i++) acc[a][nb][i] = 0.f;

    // stage loader: A 4 chunks/thread, B 8 chunks/thread (16B each)
    #define LOAD_STAGE(sidx, kbyte) do {                                        \
        uint32_t s_ = sb + (uint32_t)(sidx) * STAGE_SZ;                          \
        _Pragma("unroll")                                                        \
        for (int j = 0; j < 4; j++) {                                            \
            int idx = tid + j * 256;                                             \
            int row = idx >> 3, cb = idx & 7;                                    \
            cp16(s_ + SWZ128(row, cb),                                           \
                 pA + aBase + (size_t)row * K2 + (kbyte) + cb * 16);             \
        }                                                                        \
        _Pragma("unroll")                                                        \
        for (int j = 0; j < 8; j++) {                                            \
            int idx = tid + j * 256;                                             \
            int row = idx >> 3, cb = idx & 7;                                    \
            cp16(s_ + ST_A + SWZ128(row, cb),                                    \
                 pB + bBase + (size_t)row * K2 + (kbyte) + cb * 16);             \
        }                                                                        \
    } while (0)

    LOAD_STAGE(0, 0);
    CP_COMMIT();

    for (int c = 0; c < nch; c++) {
        CP_WAIT0();
        __syncthreads();
        if (c + 1 < nch) {
            LOAD_STAGE((c + 1) & 1, (size_t)(c + 1) * 128);
            CP_COMMIT();
        }
        uint32_t s = sb + (uint32_t)(c & 1) * STAGE_SZ;
        #pragma unroll
        for (int ks = 0; ks < 4; ks++) {
            uint32_t af[4][4];
            int acb = ks * 2 + a_cbo;
            #pragma unroll
            for (int a = 0; a < 4; a++)
                ldsm4(af[a], s + SWZ128(a_row + a * 16, acb));
            uint32_t bf[4][4];
            int bcb = ks * 2 + b_cbo;
            #pragma unroll
            for (int p = 0; p < 4; p++)
                ldsm4(bf[p], s + ST_A + SWZ128(b_row + p * 16, bcb));
            #pragma unroll
            for (int p = 0; p < 4; p++)
                #pragma unroll
                for (int h = 0; h < 2; h++) {
                    int nb = p * 2 + h;
                    #pragma unroll
                    for (int a = 0; a < 4; a++)
                        mma16816(acc[a][nb], af[a], bf[p][2*h], bf[p][2*h+1]);
                }
        }
    }
    #undef LOAD_STAGE

    // ---- epilogue ----
    int erow0 = bm * 128 + wm * 64 + (lane >> 2);
    int ecol0 = bn * 256 + wn * 64 + 2 * (lane & 3);

    #pragma unroll
    for (int a = 0; a < 4; a++) {
        #pragma unroll
        for (int nb = 0; nb < 8; nb++) {
            int gn = ecol0 + nb * 8;
            #pragma unroll
            for (int half = 0; half < 2; half++) {
                int gm = erow0 + a * 16 + half * 8;
                float v0 = acc[a][nb][half * 2 + 0];
                float v1 = acc[a][nb][half * 2 + 1];
                if (EPI == 0) {
                    int which = gn >> 10;
                    int w = gn & (E_ - 1);
                    int hh = w >> 6, dd = w & 63;
                    int bk = gm / T_, tt = gm - bk * T_;
                    __half* dst = (which == 0) ? qo : (which == 1) ? ko : vo;
                    uint32_t o = f22u(v0, v1);
                    *(uint32_t*)(dst + (((size_t)(bk * H_ + hh)) * T_ + tt) * HS_ + dd) = o;
                } else if (EPI == 1) {
                    const float2 bv = *(const float2*)(bias + gn);
                    const float2 rv = *(const float2*)(resid + (size_t)gm * N + gn);
                    float2 o = {v0 + bv.x + rv.x, v1 + bv.y + rv.y};
                    *(float2*)(outf + (size_t)gm * N + gn) = o;
                } else {
                    const float2 bv = *(const float2*)(bias + gn);
                    uint32_t o = f22u(fmaxf(v0 + bv.x, 0.f), fmaxf(v1 + bv.y, 0.f));
                    *(uint32_t*)(outh + (size_t)gm * N + gn) = o;
                }
            }
        }
    }
}

// ================= HMMA flash attention =========================================
// fp16 QKV [B,H,T,HS], HS=64. Block: 128 thr (4 warps), 64-query tile.
#define KVOFF(row, cb) SWZ128(row, cb)

__global__ void __launch_bounds__(128) attn_kernel(
    const __half* __restrict__ Qg, const __half* __restrict__ Kg,
    const __half* __restrict__ Vg, __half* __restrict__ Og)
{
    __shared__ __half Qs[4096];
    __shared__ __half Ks[2][4096];
    __shared__ __half Vs[2][4096];

    int qt = blockIdx.x, bh = blockIdx.y;
    int q0 = qt * 64;
    int tid = threadIdx.x, lane = tid & 31, w = tid >> 5;
    const char* qg = (const char*)(Qg + (size_t)bh * T_ * HS_) + (size_t)q0 * 128;
    const char* kg = (const char*)(Kg + (size_t)bh * T_ * HS_);
    const char* vg = (const char*)(Vg + (size_t)bh * T_ * HS_);
    uint32_t sq = smem_to_u32(Qs);
    uint32_t sk0 = smem_to_u32(Ks[0]), sk1 = smem_to_u32(Ks[1]);
    uint32_t sv0 = smem_to_u32(Vs[0]), sv1 = smem_to_u32(Vs[1]);

    #pragma unroll
    for (int j = 0; j < 4; j++) {
        int i = tid + j * 128;
        int row = i >> 3, cb = i & 7;
        uint32_t o = KVOFF(row, cb);
        size_t g = (size_t)row * 128 + cb * 16;
        cp16(sq + o, qg + g);
        cp16(sk0 + o, kg + g);
        cp16(sv0 + o, vg + g);
    }
    CP_COMMIT();
    CP_WAIT0();
    __syncthreads();

    int mid = lane >> 3, r8 = lane & 7;
    uint32_t afr[4][4];
    #pragma unroll
    for (int s = 0; s < 4; s++) {
        int row = 16 * w + ((mid & 1) << 3) + r8;
        int cb = s * 2 + (mid >> 1);
        ldsm4(afr[s], sq + KVOFF(row, cb));
    }

    float o_acc[8][4];
    #pragma unroll
    for (int a = 0; a < 8; a++)
        #pragma unroll
        for (int i = 0; i < 4; i++) o_acc[a][i] = 0.f;
    float mr0 = -1e30f, mr1 = -1e30f, lr0 = 0.f, lr1 = 0.f;

    int nkt = qt + 1;
    int myrow0 = 16 * w + (lane >> 2);
    int mycol0 = 2 * (lane & 3);

    for (int kt = 0; kt < nkt; kt++) {
        __syncthreads();
        if (kt + 1 < nkt) {
            uint32_t dk = (kt & 1) ? sk0 : sk1;
            uint32_t dv = (kt & 1) ? sv0 : sv1;
            const char* kg_ = kg + (size_t)(kt + 1) * 64 * 128;
            const char* vg_ = vg + (size_t)(kt + 1) * 64 * 128;
            #pragma unroll
            for (int j = 0; j < 4; j++) {
                int i = tid + j * 128;
                int row = i >> 3, cb = i & 7;
                uint32_t o = KVOFF(row, cb);
                size_t g = (size_t)row * 128 + cb * 16;
                cp16(dk + o, kg_ + g);
                cp16(dv + o, vg_ + g);
            }
        }
        CP_COMMIT();
        CP_WAIT1();
        __syncthreads();

        uint32_t skb = (kt & 1) ? sk1 : sk0;
        uint32_t svb = (kt & 1) ? sv1 : sv0;

        float sA[8][4];
        #pragma unroll
        for (int e = 0; e < 8; e++)
            #pragma unroll
            for (int i = 0; i < 4; i++) sA[e][i] = 0.f;
        #pragma unroll
        for (int s = 0; s < 4; s++) {
            #pragma unroll
            for (int j = 0; j < 4; j++) {
                int row = j * 16 + ((mid >> 1) << 3) + r8;
                int cb = s * 2 + (mid & 1);
                uint32_t bk[4];
                ldsm4(bk, skb + KVOFF(row, cb));
                mma16816(sA[2*j],   afr[s], bk[0], bk[1]);
                mma16816(sA[2*j+1], afr[s], bk[2], bk[3]);
            }
        }

        #pragma unroll
        for (int e = 0; e < 8; e++)
            #pragma unroll
            for (int i = 0; i < 4; i++) sA[e][i] *= 0.03125f;
        if (kt == qt) {
            #pragma unroll
            for (int e = 0; e < 8; e++) {
                int kc = e * 8 + mycol0;
                if (kc     > myrow0)     sA[e][0] = -1e30f;
                if (kc + 1 > myrow0)     sA[e][1] = -1e30f;
                if (kc     > myrow0 + 8) sA[e][2] = -1e30f;
                if (kc + 1 > myrow0 + 8) sA[e][3] = -1e30f;
            }
        }

        float mx0 = -1e30f, mx1 = -1e30f;
        #pragma unroll
        for (int e = 0; e < 8; e++) {
            mx0 = fmaxf(mx0, fmaxf(sA[e][0], sA[e][1]));
            mx1 = fmaxf(mx1, fmaxf(sA[e][2], sA[e][3]));
        }
        mx0 = fmaxf(mx0, __shfl_xor_sync(0xffffffffu, mx0, 1));
        mx0 = fmaxf(mx0, __shfl_xor_sync(0xffffffffu, mx0, 2));
        mx1 = fmaxf(mx1, __shfl_xor_sync(0xffffffffu, mx1, 1));
        mx1 = fmaxf(mx1, __shfl_xor_sync(0xffffffffu, mx1, 2));
        float mn0 = fmaxf(mr0, mx0), mn1 = fmaxf(mr1, mx1);
        float al0 = __expf(mr0 - mn0), al1 = __expf(mr1 - mn1);
        mr0 = mn0; mr1 = mn1;

        float sum0 = 0.f, sum1 = 0.f;
        uint32_t pa[4][4];
        #pragma unroll
        for (int e = 0; e < 8; e++) {
            float p0 = __expf(sA[e][0] - mn0);
            float p1 = __expf(sA[e][1] - mn0);
            float p2 = __expf(sA[e][2] - mn1);
            float p3 = __expf(sA[e][3] - mn1);
            sum0 += p0 + p1; sum1 += p2 + p3;
            int t = e >> 1, od = (e & 1) * 2;
            pa[t][od]     = f22u(p0, p1);
            pa[t][od + 1] = f22u(p2, p3);
        }
        sum0 += __shfl_xor_sync(0xffffffffu, sum0, 1);
        sum0 += __shfl_xor_sync(0xffffffffu, sum0, 2);
        sum1 += __shfl_xor_sync(0xffffffffu, sum1, 1);
        sum1 += __shfl_xor_sync(0xffffffffu, sum1, 2);
        lr0 = lr0 * al0 + sum0;
        lr1 = lr1 * al1 + sum1;

        #pragma unroll
        for (int a = 0; a < 8; a++) {
            o_acc[a][0] *= al0; o_acc[a][1] *= al0;
            o_acc[a][2] *= al1; o_acc[a][3] *= al1;
        }

        #pragma unroll
        for (int t = 0; t < 4; t++) {
            #pragma unroll
            for (int j = 0; j < 4; j++) {
                int row = t * 16 + ((mid & 1) << 3) + r8;
                int cb = j * 2 + (mid >> 1);
                uint32_t bv[4];
                ldsm4t(bv, svb + KVOFF(row, cb));
                mma16816(o_acc[2*j],   pa[t], bv[0], bv[1]);
                mma16816(o_acc[2*j+1], pa[t], bv[2], bv[3]);
            }
        }
    }

    float inv0 = 1.0f / lr0, inv1 = 1.0f / lr1;
    int b = bh >> 4, h = bh & 15;
    int gr0 = q0 + myrow0, gr1 = gr0 + 8;
    #pragma unroll
    for (int a = 0; a < 8; a++) {
        int d = a * 8 + mycol0;
        *(uint32_t*)(Og + (((size_t)(b * T_ + gr0)) * H_ + h) * HS_ + d) =
            f22u(o_acc[a][0] * inv0, o_acc[a][1] * inv0);
        *(uint32_t*)(Og + (((size_t)(b * T_ + gr1)) * H_ + h) * HS_ + d) =
            f22u(o_acc[a][2] * inv1, o_acc[a][3] * inv1);
    }
}

// ---------------- launch --------------------------------------------------------
extern "C" void kernel_launch(void* const* d_in, const int* in_sizes, int n_in,
                              void* d_out, int out_size)
{
    const float* x    = (const float*)d_in[0];
    const float* Wq   = (const float*)d_in[1];
    const float* Wk   = (const float*)d_in[2];
    const float* Wv   = (const float*)d_in[3];
    const float* Wo   = (const float*)d_in[4];
    const float* bo   = (const float*)d_in[5];
    const float* W1   = (const float*)d_in[6];
    const float* b1   = (const float*)d_in[7];
    const float* W2   = (const float*)d_in[8];
    const float* b2   = (const float*)d_in[9];
    const float* ln1w = (const float*)d_in[10];
    const float* ln1b = (const float*)d_in[11];
    const float* ln2w = (const float*)d_in[12];
    const float* ln2b = (const float*)d_in[13];
    float* out = (float*)d_out;

    __half *ph, *pat, *pf1, *pq, *pk, *pv, *wqkv, *wo, *w1, *w2;
    cudaGetSymbolAddress((void**)&ph,   g_h);
    cudaGetSymbolAddress((void**)&pat,  g_at);
    cudaGetSymbolAddress((void**)&pf1,  g_f1);
    cudaGetSymbolAddress((void**)&pq,   g_q);
    cudaGetSymbolAddress((void**)&pk,   g_k);
    cudaGetSymbolAddress((void**)&pv,   g_v);
    cudaGetSymbolAddress((void**)&wqkv, g_wqkv);
    cudaGetSymbolAddress((void**)&wo,   g_wo);
    cudaGetSymbolAddress((void**)&w1,   g_w1);
    cudaGetSymbolAddress((void**)&w2,   g_w2);

    cudaFuncSetAttribute(tgemm_kernel<0>, cudaFuncAttributeMaxDynamicSharedMemorySize, SMEM_GEMM);
    cudaFuncSetAttribute(tgemm_kernel<1>, cudaFuncAttributeMaxDynamicSharedMemorySize, SMEM_GEMM);
    cudaFuncSetAttribute(tgemm_kernel<2>, cudaFuncAttributeMaxDynamicSharedMemorySize, SMEM_GEMM);

    dim3 tb(32, 8);

    // weight prep (transpose to fp16 [N,K])
    trans_qkv_kernel<<<dim3(2, 32, 48), tb>>>(Wq, Wk, Wv, wqkv);
    trans_kernel<<<dim3(32, 32), tb>>>(Wo, E_, E_, wo);
    trans_kernel<<<dim3(128, 32), tb>>>(W1, E_, FF_, w1);
    trans_kernel<<<dim3(32, 128), tb>>>(W2, FF_, E_, w2);

    // h = LN1(x) -> fp16
    ln_kernel<<<M_, 256>>>(x, ln1w, ln1b, ph);

    // q,k,v = h @ Wqkv (scatter fp16 [B,H,T,HS])
    tgemm_kernel<0><<<dim3(3*E_/256, M_/128), 256, SMEM_GEMM>>>(
        ph, wqkv, M_, 3*E_, E_,
        nullptr, nullptr, nullptr, nullptr, pq, pk, pv);

    // attention (HMMA flash) -> fp16 [B,T,H,HS]
    attn_kernel<<<dim3(T_/64, B_*H_), 128>>>(pq, pk, pv, pat);

    // x1 = x + attn @ Wo + bo  (fp32, into d_out)
    tgemm_kernel<1><<<dim3(E_/256, M_/128), 256, SMEM_GEMM>>>(
        pat, wo, M_, E_, E_,
        bo, x, out, nullptr, nullptr, nullptr, nullptr);

    // h2 = LN2(x1) -> fp16
    ln_kernel<<<M_, 256>>>(out, ln2w, ln2b, ph);

    // f1 = relu(h2 @ W1 + b1) -> fp16
    tgemm_kernel<2><<<dim3(FF_/256, M_/128), 256, SMEM_GEMM>>>(
        ph, w1, M_, FF_, E_,
        b1, nullptr, nullptr, pf1, nullptr, nullptr, nullptr);

    // out = x1 + f1 @ W2 + b2
    tgemm_kernel<1><<<dim3(E_/256, M_/128), 256, SMEM_GEMM>>>(
        pf1, w2, M_, E_, FF_,
        b2, out, out, nullptr, nullptr, nullptr, nullptr);
}

// round 15
// speedup vs baseline: 8.8554x; 1.0151x over previous
#include <cuda_runtime.h>
#include <cuda_fp16.h>
#include <cstdint>
#include <cstddef>

// Problem constants
#define B_  64
#define T_  320
#define E_  1024
#define H_  16
#define HS_ 64
#define M_  (B_*T_)      // 20480 tokens
#define FF_ (4*E_)       // 4096

// ===================== baseline-PTX helpers (no 'a'-arch features) =============
__device__ __forceinline__ uint32_t smem_to_u32(const void* p) {
    uint32_t a;
    asm("{ .reg .u64 t; cvta.to.shared.u64 t, %1; cvt.u32.u64 %0, t; }" : "=r"(a) : "l"(p));
    return a;
}
__device__ __forceinline__ void cp16(uint32_t s, const void* g) {
    asm volatile("cp.async.cg.shared.global [%0], [%1], 16;" :: "r"(s), "l"(g));
}
#define CP_COMMIT() asm volatile("cp.async.commit_group;" ::: "memory")
#define CP_WAIT0()  asm volatile("cp.async.wait_group 0;"  ::: "memory")
#define CP_WAIT1()  asm volatile("cp.async.wait_group 1;"  ::: "memory")

__device__ __forceinline__ void ldsm4(uint32_t* r, uint32_t addr) {
    asm volatile("ldmatrix.sync.aligned.m8n8.x4.shared.b16 {%0,%1,%2,%3}, [%4];"
        : "=r"(r[0]), "=r"(r[1]), "=r"(r[2]), "=r"(r[3]) : "r"(addr));
}
__device__ __forceinline__ void ldsm4t(uint32_t* r, uint32_t addr) {
    asm volatile("ldmatrix.sync.aligned.m8n8.x4.trans.shared.b16 {%0,%1,%2,%3}, [%4];"
        : "=r"(r[0]), "=r"(r[1]), "=r"(r[2]), "=r"(r[3]) : "r"(addr));
}
// fp16 MMA, fp32 accumulate
__device__ __forceinline__ void mma16816(float* c, const uint32_t* a,
                                         uint32_t b0, uint32_t b1) {
    asm volatile(
        "mma.sync.aligned.m16n8k16.row.col.f32.f16.f16.f32 "
        "{%0,%1,%2,%3},{%4,%5,%6,%7},{%8,%9},{%0,%1,%2,%3};"
        : "+f"(c[0]), "+f"(c[1]), "+f"(c[2]), "+f"(c[3])
        : "r"(a[0]), "r"(a[1]), "r"(a[2]), "r"(a[3]), "r"(b0), "r"(b1));
}
__device__ __forceinline__ uint32_t f22u(float a, float b) {
    __half2 h = __float22half2_rn(make_float2(a, b));
    return *(uint32_t*)&h;
}

// 128B-row XOR swizzle: conflict-free for cp.async fill and ldmatrix reads
#define SWZ128(row, cb) ((uint32_t)(((row) << 7) + ((((cb) ^ ((row) & 7))) << 4)))

// ===================== device scratch (no allocations allowed) ==================
__device__ __half g_h   [(size_t)M_*E_];     // LN output fp16
__device__ __half g_at  [(size_t)M_*E_];     // attention out [B,T,H,HS]
__device__ __half g_f1  [(size_t)M_*FF_];    // relu(h2@W1+b1)
__device__ __half g_q   [(size_t)M_*E_];     // [B,H,T,HS] fp16
__device__ __half g_k   [(size_t)M_*E_];
__device__ __half g_v   [(size_t)M_*E_];
__device__ __half g_wqkv[(size_t)3*E_*E_];   // [N=3E, K=E] fp16
__device__ __half g_wo  [(size_t)E_*E_];     // [N=E, K=E]
__device__ __half g_w1  [(size_t)FF_*E_];    // [N=4E, K=E]
__device__ __half g_w2  [(size_t)E_*FF_];    // [N=E, K=4E]

// ============ weight prep: transpose fp32 [K,N] -> fp16 [N,K] ===================
__global__ void trans_kernel(const float* __restrict__ in, int K, int N,
                             __half* __restrict__ o)
{
    __shared__ float t[32][33];
    int nb = blockIdx.x * 32, kb = blockIdx.y * 32;
    int tx = threadIdx.x, ty = threadIdx.y;          // 32 x 8
    #pragma unroll
    for (int j = 0; j < 4; j++)
        t[ty + j*8][tx] = in[(size_t)(kb + ty + j*8) * N + nb + tx];
    __syncthreads();
    #pragma unroll
    for (int j = 0; j < 4; j++) {
        float v = t[tx][ty + j*8];
        int orow = nb + ty + j*8, ocol = kb + tx;
        o[(size_t)orow * K + ocol] = __float2half_rn(v);
    }
}

// Wq/Wk/Wv (H,E,HS) -> [3E rows, E cols] transposed fp16
__global__ void trans_qkv_kernel(const float* __restrict__ Wq,
                                 const float* __restrict__ Wk,
                                 const float* __restrict__ Wv,
                                 __half* __restrict__ o)
{
    __shared__ float t[32][33];
    int z = blockIdx.z;
    const float* W = (z < 16) ? Wq : (z < 32) ? Wk : Wv;
    const float* in = W + (size_t)(z & 15) * E_ * HS_;
    int nb = blockIdx.x * 32, kb = blockIdx.y * 32;
    int tx = threadIdx.x, ty = threadIdx.y;
    #pragma unroll
    for (int j = 0; j < 4; j++)
        t[ty + j*8][tx] = in[(size_t)(kb + ty + j*8) * HS_ + nb + tx];
    __syncthreads();
    #pragma unroll
    for (int j = 0; j < 4; j++) {
        float v = t[tx][ty + j*8];
        int orow = z * 64 + nb + ty + j*8;
        int ocol = kb + tx;
        o[(size_t)orow * E_ + ocol] = __float2half_rn(v);
    }
}

// ================= layernorm -> fp16 ============================================
__global__ void __launch_bounds__(256) ln_kernel(const float* __restrict__ x,
                                                 const float* __restrict__ w,
                                                 const float* __restrict__ b,
                                                 __half* __restrict__ o)
{
    int row = blockIdx.x;
    int t = threadIdx.x;
    float4 v = ((const float4*)(x + (size_t)row * E_))[t];
    float s  = v.x + v.y + v.z + v.w;
    float sq = v.x*v.x + v.y*v.y + v.z*v.z + v.w*v.w;
    #pragma unroll
    for (int off = 16; off; off >>= 1) {
        s  += __shfl_xor_sync(0xffffffffu, s,  off);
        sq += __shfl_xor_sync(0xffffffffu, sq, off);
    }
    __shared__ float ss[8], ssq[8];
    int warp = t >> 5, lane = t & 31;
    if (lane == 0) { ss[warp] = s; ssq[warp] = sq; }
    __syncthreads();
    float tot = 0.f, totq = 0.f;
    #pragma unroll
    for (int i = 0; i < 8; i++) { tot += ss[i]; totq += ssq[i]; }
    float mu  = tot * (1.0f / E_);
    float var = totq * (1.0f / E_) - mu * mu;
    float rs  = rsqrtf(var + 1e-5f);
    float4 w4 = ((const float4*)w)[t];
    float4 b4 = ((const float4*)b)[t];
    float r0 = (v.x - mu) * rs * w4.x + b4.x;
    float r1 = (v.y - mu) * rs * w4.y + b4.y;
    float r2 = (v.z - mu) * rs * w4.z + b4.z;
    float r3 = (v.w - mu) * rs * w4.w + b4.w;
    uint2 p = { f22u(r0, r1), f22u(r2, r3) };
    ((uint2*)(o + (size_t)row * E_))[t] = p;
}

// ================= mma.sync fp16 GEMM ===========================================
// C[M,N] = A[M,K] * B[N,K]^T. 128x256 block tile, 8 warps (2x4), warp tile 64x64,
// K-chunk 64, 3-stage cp.async pipeline (prefetch distance 2).
// EPI 0: scatter fp16 q/k/v   EPI 1: fp32 out = acc+bias+resid
// EPI 2: fp16 out = relu(acc+bias)
#define ST_A     16384                 // A: 128 rows x 128B
#define ST_B     32768                 // B: 256 rows x 128B
#define STAGE_SZ (ST_A+ST_B)           // 48 KB
#define NSTAGE   3
#define SMEM_GEMM (NSTAGE*STAGE_SZ)    // 144 KB

template<int EPI>
__global__ void __launch_bounds__(256, 1) tgemm_kernel(
    const __half* __restrict__ A, const __half* __restrict__ Bw,
    int M, int N, int K,
    const float* __restrict__ bias, const float* __restrict__ resid,
    float* __restrict__ outf, __half* __restrict__ outh,
    __half* __restrict__ qo, __half* __restrict__ ko, __half* __restrict__ vo)
{
    extern __shared__ char smem[];
    uint32_t sb = smem_to_u32(smem);
    int tid  = threadIdx.x;
    int lane = tid & 31, wid = tid >> 5;
    int bm = blockIdx.y, bn = blockIdx.x;
    int wm = wid >> 2, wn = wid & 3;

    const char* pA = (const char*)A;
    const char* pB = (const char*)Bw;
    const int K2 = K * 2;                    // bytes per row
    const size_t aBase = (size_t)(bm * 128) * K2;
    const size_t bBase = (size_t)(bn * 256) * K2;
    const int nch = K >> 6;                  // 64-K chunks

    int a_row = wm * 64 + (lane & 15);
    int a_cbo = lane >> 4;                   // 0/1
    int bg = lane >> 3, br = lane & 7;
    int b_row = wn * 64 + ((bg >> 1) << 3) + br;
    int b_cbo = bg & 1;

    float acc[4][8][4];
    #pragma unroll
    for (int a = 0; a < 4; a++)
        #pragma unroll
        for (int nb = 0; nb < 8; nb++)
            #pragma unroll
            for (int i = 0; i < 4; i++) acc[a][nb][i] = 0.f;

    // stage loader: A 4 chunks/thread, B 8 chunks/thread (16B each)
    #define LOAD_STAGE(sidx, kbyte) do {                                        \
        uint32_t s_ = sb + (uint32_t)(sidx) * STAGE_SZ;                          \
        _Pragma("unroll")                                                        \
        for (int j = 0; j < 4; j++) {                                            \
            int idx = tid + j * 256;                                             \
            int row = idx >> 3, cb = idx & 7;                                    \
            cp16(s_ + SWZ128(row, cb),                                           \
                 pA + aBase + (size_t)row * K2 + (kbyte) + cb * 16);             \
        }                                                                        \
        _Pragma("unroll")                                                        \
        for (int j = 0; j < 8; j++) {                                            \
            int idx = tid + j * 256;                                             \
            int row = idx >> 3, cb = idx & 7;                                    \
            cp16(s_ + ST_A + SWZ128(row, cb),                                    \
                 pB + bBase + (size_t)row * K2 + (kbyte) + cb * 16);             \
        }                                                                        \
    } while (0)

    // prologue: chunks 0 and 1 in flight
    LOAD_STAGE(0, 0);
    CP_COMMIT();
    LOAD_STAGE(1, 128);
    CP_COMMIT();

    int sidx = 0;                            // stage of chunk c
    for (int c = 0; c < nch; c++) {
        CP_WAIT1();                          // chunk c's group complete
        __syncthreads();
        // prefetch chunk c+2 (always commit to keep group counts uniform)
        if (c + 2 < nch) {
            int nsi = sidx + 2; if (nsi >= NSTAGE) nsi -= NSTAGE;
            LOAD_STAGE(nsi, (size_t)(c + 2) * 128);
        }
        CP_COMMIT();

        uint32_t s = sb + (uint32_t)sidx * STAGE_SZ;
        #pragma unroll
        for (int ks = 0; ks < 4; ks++) {
            uint32_t af[4][4];
            int acb = ks * 2 + a_cbo;
            #pragma unroll
            for (int a = 0; a < 4; a++)
                ldsm4(af[a], s + SWZ128(a_row + a * 16, acb));
            uint32_t bf[4][4];
            int bcb = ks * 2 + b_cbo;
            #pragma unroll
            for (int p = 0; p < 4; p++)
                ldsm4(bf[p], s + ST_A + SWZ128(b_row + p * 16, bcb));
            #pragma unroll
            for (int p = 0; p < 4; p++)
                #pragma unroll
                for (int h = 0; h < 2; h++) {
                    int nb = p * 2 + h;
                    #pragma unroll
                    for (int a = 0; a < 4; a++)
                        mma16816(acc[a][nb], af[a], bf[p][2*h], bf[p][2*h+1]);
                }
        }
        sidx++; if (sidx >= NSTAGE) sidx = 0;
    }
    #undef LOAD_STAGE

    // ---- epilogue ----
    int erow0 = bm * 128 + wm * 64 + (lane >> 2);
    int ecol0 = bn * 256 + wn * 64 + 2 * (lane & 3);

    #pragma unroll
    for (int a = 0; a < 4; a++) {
        #pragma unroll
        for (int nb = 0; nb < 8; nb++) {
            int gn = ecol0 + nb * 8;
            #pragma unroll
            for (int half = 0; half < 2; half++) {
                int gm = erow0 + a * 16 + half * 8;
                float v0 = acc[a][nb][half * 2 + 0];
                float v1 = acc[a][nb][half * 2 + 1];
                if (EPI == 0) {
                    int which = gn >> 10;
                    int w = gn & (E_ - 1);
                    int hh = w >> 6, dd = w & 63;
                    int bk = gm / T_, tt = gm - bk * T_;
                    __half* dst = (which == 0) ? qo : (which == 1) ? ko : vo;
                    uint32_t o = f22u(v0, v1);
                    *(uint32_t*)(dst + (((size_t)(bk * H_ + hh)) * T_ + tt) * HS_ + dd) = o;
                } else if (EPI == 1) {
                    const float2 bv = *(const float2*)(bias + gn);
                    const float2 rv = *(const float2*)(resid + (size_t)gm * N + gn);
                    float2 o = {v0 + bv.x + rv.x, v1 + bv.y + rv.y};
                    *(float2*)(outf + (size_t)gm * N + gn) = o;
                } else {
                    const float2 bv = *(const float2*)(bias + gn);
                    uint32_t o = f22u(fmaxf(v0 + bv.x, 0.f), fmaxf(v1 + bv.y, 0.f));
                    *(uint32_t*)(outh + (size_t)gm * N + gn) = o;
                }
            }
        }
    }
}

// ================= HMMA flash attention =========================================
// fp16 QKV [B,H,T,HS], HS=64. Block: 128 thr (4 warps), 64-query tile.
#define KVOFF(row, cb) SWZ128(row, cb)

__global__ void __launch_bounds__(128) attn_kernel(
    const __half* __restrict__ Qg, const __half* __restrict__ Kg,
    const __half* __restrict__ Vg, __half* __restrict__ Og)
{
    __shared__ __half Qs[4096];
    __shared__ __half Ks[2][4096];
    __shared__ __half Vs[2][4096];

    int qt = blockIdx.x, bh = blockIdx.y;
    int q0 = qt * 64;
    int tid = threadIdx.x, lane = tid & 31, w = tid >> 5;
    const char* qg = (const char*)(Qg + (size_t)bh * T_ * HS_) + (size_t)q0 * 128;
    const char* kg = (const char*)(Kg + (size_t)bh * T_ * HS_);
    const char* vg = (const char*)(Vg + (size_t)bh * T_ * HS_);
    uint32_t sq = smem_to_u32(Qs);
    uint32_t sk0 = smem_to_u32(Ks[0]), sk1 = smem_to_u32(Ks[1]);
    uint32_t sv0 = smem_to_u32(Vs[0]), sv1 = smem_to_u32(Vs[1]);

    #pragma unroll
    for (int j = 0; j < 4; j++) {
        int i = tid + j * 128;
        int row = i >> 3, cb = i & 7;
        uint32_t o = KVOFF(row, cb);
        size_t g = (size_t)row * 128 + cb * 16;
        cp16(sq + o, qg + g);
        cp16(sk0 + o, kg + g);
        cp16(sv0 + o, vg + g);
    }
    CP_COMMIT();
    CP_WAIT0();
    __syncthreads();

    int mid = lane >> 3, r8 = lane & 7;
    uint32_t afr[4][4];
    #pragma unroll
    for (int s = 0; s < 4; s++) {
        int row = 16 * w + ((mid & 1) << 3) + r8;
        int cb = s * 2 + (mid >> 1);
        ldsm4(afr[s], sq + KVOFF(row, cb));
    }

    float o_acc[8][4];
    #pragma unroll
    for (int a = 0; a < 8; a++)
        #pragma unroll
        for (int i = 0; i < 4; i++) o_acc[a][i] = 0.f;
    float mr0 = -1e30f, mr1 = -1e30f, lr0 = 0.f, lr1 = 0.f;

    int nkt = qt + 1;
    int myrow0 = 16 * w + (lane >> 2);
    int mycol0 = 2 * (lane & 3);

    for (int kt = 0; kt < nkt; kt++) {
        __syncthreads();
        if (kt + 1 < nkt) {
            uint32_t dk = (kt & 1) ? sk0 : sk1;
            uint32_t dv = (kt & 1) ? sv0 : sv1;
            const char* kg_ = kg + (size_t)(kt + 1) * 64 * 128;
            const char* vg_ = vg + (size_t)(kt + 1) * 64 * 128;
            #pragma unroll
            for (int j = 0; j < 4; j++) {
                int i = tid + j * 128;
                int row = i >> 3, cb = i & 7;
                uint32_t o = KVOFF(row, cb);
                size_t g = (size_t)row * 128 + cb * 16;
                cp16(dk + o, kg_ + g);
                cp16(dv + o, vg_ + g);
            }
        }
        CP_COMMIT();
        CP_WAIT1();
        __syncthreads();

        uint32_t skb = (kt & 1) ? sk1 : sk0;
        uint32_t svb = (kt & 1) ? sv1 : sv0;

        float sA[8][4];
        #pragma unroll
        for (int e = 0; e < 8; e++)
            #pragma unroll
            for (int i = 0; i < 4; i++) sA[e][i] = 0.f;
        #pragma unroll
        for (int s = 0; s < 4; s++) {
            #pragma unroll
            for (int j = 0; j < 4; j++) {
                int row = j * 16 + ((mid >> 1) << 3) + r8;
                int cb = s * 2 + (mid & 1);
                uint32_t bk[4];
                ldsm4(bk, skb + KVOFF(row, cb));
                mma16816(sA[2*j],   afr[s], bk[0], bk[1]);
                mma16816(sA[2*j+1], afr[s], bk[2], bk[3]);
            }
        }

        #pragma unroll
        for (int e = 0; e < 8; e++)
            #pragma unroll
            for (int i = 0; i < 4; i++) sA[e][i] *= 0.03125f;
        if (kt == qt) {
            #pragma unroll
            for (int e = 0; e < 8; e++) {
                int kc = e * 8 + mycol0;
                if (kc     > myrow0)     sA[e][0] = -1e30f;
                if (kc + 1 > myrow0)     sA[e][1] = -1e30f;
                if (kc     > myrow0 + 8) sA[e][2] = -1e30f;
                if (kc + 1 > myrow0 + 8) sA[e][3] = -1e30f;
            }
        }

        float mx0 = -1e30f, mx1 = -1e30f;
        #pragma unroll
        for (int e = 0; e < 8; e++) {
            mx0 = fmaxf(mx0, fmaxf(sA[e][0], sA[e][1]));
            mx1 = fmaxf(mx1, fmaxf(sA[e][2], sA[e][3]));
        }
        mx0 = fmaxf(mx0, __shfl_xor_sync(0xffffffffu, mx0, 1));
        mx0 = fmaxf(mx0, __shfl_xor_sync(0xffffffffu, mx0, 2));
        mx1 = fmaxf(mx1, __shfl_xor_sync(0xffffffffu, mx1, 1));
        mx1 = fmaxf(mx1, __shfl_xor_sync(0xffffffffu, mx1, 2));
        float mn0 = fmaxf(mr0, mx0), mn1 = fmaxf(mr1, mx1);
        float al0 = __expf(mr0 - mn0), al1 = __expf(mr1 - mn1);
        mr0 = mn0; mr1 = mn1;

        float sum0 = 0.f, sum1 = 0.f;
        uint32_t pa[4][4];
        #pragma unroll
        for (int e = 0; e < 8; e++) {
            float p0 = __expf(sA[e][0] - mn0);
            float p1 = __expf(sA[e][1] - mn0);
            float p2 = __expf(sA[e][2] - mn1);
            float p3 = __expf(sA[e][3] - mn1);
            sum0 += p0 + p1; sum1 += p2 + p3;
            int t = e >> 1, od = (e & 1) * 2;
            pa[t][od]     = f22u(p0, p1);
            pa[t][od + 1] = f22u(p2, p3);
        }
        sum0 += __shfl_xor_sync(0xffffffffu, sum0, 1);
        sum0 += __shfl_xor_sync(0xffffffffu, sum0, 2);
        sum1 += __shfl_xor_sync(0xffffffffu, sum1, 1);
        sum1 += __shfl_xor_sync(0xffffffffu, sum1, 2);
        lr0 = lr0 * al0 + sum0;
        lr1 = lr1 * al1 + sum1;

        #pragma unroll
        for (int a = 0; a < 8; a++) {
            o_acc[a][0] *= al0; o_acc[a][1] *= al0;
            o_acc[a][2] *= al1; o_acc[a][3] *= al1;
        }

        #pragma unroll
        for (int t = 0; t < 4; t++) {
            #pragma unroll
            for (int j = 0; j < 4; j++) {
                int row = t * 16 + ((mid & 1) << 3) + r8;
                int cb = j * 2 + (mid >> 1);
                uint32_t bv[4];
                ldsm4t(bv, svb + KVOFF(row, cb));
                mma16816(o_acc[2*j],   pa[t], bv[0], bv[1]);
                mma16816(o_acc[2*j+1], pa[t], bv[2], bv[3]);
            }
        }
    }

    float inv0 = 1.0f / lr0, inv1 = 1.0f / lr1;
    int b = bh >> 4, h = bh & 15;
    int gr0 = q0 + myrow0, gr1 = gr0 + 8;
    #pragma unroll
    for (int a = 0; a < 8; a++) {
        int d = a * 8 + mycol0;
        *(uint32_t*)(Og + (((size_t)(b * T_ + gr0)) * H_ + h) * HS_ + d) =
            f22u(o_acc[a][0] * inv0, o_acc[a][1] * inv0);
        *(uint32_t*)(Og + (((size_t)(b * T_ + gr1)) * H_ + h) * HS_ + d) =
            f22u(o_acc[a][2] * inv1, o_acc[a][3] * inv1);
    }
}

// ---------------- launch --------------------------------------------------------
extern "C" void kernel_launch(void* const* d_in, const int* in_sizes, int n_in,
                              void* d_out, int out_size)
{
    const float* x    = (const float*)d_in[0];
    const float* Wq   = (const float*)d_in[1];
    const float* Wk   = (const float*)d_in[2];
    const float* Wv   = (const float*)d_in[3];
    const float* Wo   = (const float*)d_in[4];
    const float* bo   = (const float*)d_in[5];
    const float* W1   = (const float*)d_in[6];
    const float* b1   = (const float*)d_in[7];
    const float* W2   = (const float*)d_in[8];
    const float* b2   = (const float*)d_in[9];
    const float* ln1w = (const float*)d_in[10];
    const float* ln1b = (const float*)d_in[11];
    const float* ln2w = (const float*)d_in[12];
    const float* ln2b = (const float*)d_in[13];
    float* out = (float*)d_out;

    __half *ph, *pat, *pf1, *pq, *pk, *pv, *wqkv, *wo, *w1, *w2;
    cudaGetSymbolAddress((void**)&ph,   g_h);
    cudaGetSymbolAddress((void**)&pat,  g_at);
    cudaGetSymbolAddress((void**)&pf1,  g_f1);
    cudaGetSymbolAddress((void**)&pq,   g_q);
    cudaGetSymbolAddress((void**)&pk,   g_k);
    cudaGetSymbolAddress((void**)&pv,   g_v);
    cudaGetSymbolAddress((void**)&wqkv, g_wqkv);
    cudaGetSymbolAddress((void**)&wo,   g_wo);
    cudaGetSymbolAddress((void**)&w1,   g_w1);
    cudaGetSymbolAddress((void**)&w2,   g_w2);

    cudaFuncSetAttribute(tgemm_kernel<0>, cudaFuncAttributeMaxDynamicSharedMemorySize, SMEM_GEMM);
    cudaFuncSetAttribute(tgemm_kernel<1>, cudaFuncAttributeMaxDynamicSharedMemorySize, SMEM_GEMM);
    cudaFuncSetAttribute(tgemm_kernel<2>, cudaFuncAttributeMaxDynamicSharedMemorySize, SMEM_GEMM);

    dim3 tb(32, 8);

    // weight prep (transpose to fp16 [N,K])
    trans_qkv_kernel<<<dim3(2, 32, 48), tb>>>(Wq, Wk, Wv, wqkv);
    trans_kernel<<<dim3(32, 32), tb>>>(Wo, E_, E_, wo);
    trans_kernel<<<dim3(128, 32), tb>>>(W1, E_, FF_, w1);
    trans_kernel<<<dim3(32, 128), tb>>>(W2, FF_, E_, w2);

    // h = LN1(x) -> fp16
    ln_kernel<<<M_, 256>>>(x, ln1w, ln1b, ph);

    // q,k,v = h @ Wqkv (scatter fp16 [B,H,T,HS])
    tgemm_kernel<0><<<dim3(3*E_/256, M_/128), 256, SMEM_GEMM>>>(
        ph, wqkv, M_, 3*E_, E_,
        nullptr, nullptr, nullptr, nullptr, pq, pk, pv);

    // attention (HMMA flash) -> fp16 [B,T,H,HS]
    attn_kernel<<<dim3(T_/64, B_*H_), 128>>>(pq, pk, pv, pat);

    // x1 = x + attn @ Wo + bo  (fp32, into d_out)
    tgemm_kernel<1><<<dim3(E_/256, M_/128), 256, SMEM_GEMM>>>(
        pat, wo, M_, E_, E_,
        bo, x, out, nullptr, nullptr, nullptr, nullptr);

    // h2 = LN2(x1) -> fp16
    ln_kernel<<<M_, 256>>>(out, ln2w, ln2b, ph);

    // f1 = relu(h2 @ W1 + b1) -> fp16
    tgemm_kernel<2><<<dim3(FF_/256, M_/128), 256, SMEM_GEMM>>>(
        ph, w1, M_, FF_, E_,
        b1, nullptr, nullptr, pf1, nullptr, nullptr, nullptr);

    // out = x1 + f1 @ W2 + b2
    tgemm_kernel<1><<<dim3(E_/256, M_/128), 256, SMEM_GEMM>>>(
        pf1, w2, M_, E_, FF_,
        b2, out, out, nullptr, nullptr, nullptr, nullptr);
}